// round 4
// baseline (speedup 1.0000x reference)
#include <cuda_runtime.h>
#include <math.h>
#include <stdint.h>

// Problem constants
#define BATCH 4
#define SEQ   2048
#define DMODEL 1024
#define NH    16
#define DHD   64
#define MTOT  (BATCH*SEQ)      // 8192
#define N_QKV (3*DMODEL)       // 3072

// ---------------- scratch (static device globals; no allocation) ----------------
__device__ __align__(16) float g_q [(size_t)BATCH*NH*SEQ*DHD];
__device__ __align__(16) float g_k [(size_t)BATCH*NH*SEQ*DHD];
__device__ __align__(16) float g_v [(size_t)BATCH*NH*SEQ*DHD];
__device__ __align__(16) float g_ao[(size_t)MTOT*DMODEL];
__device__ float g_cos[SEQ*32];
__device__ float g_sin[SEQ*32];

// ---------------- RoPE tables ----------------
// angle computed in fp32 (matches jax fp32 table), trig in double for accuracy
// (safe even under --use_fast_math; angles reach ~2047 rad).
__global__ void rope_table_kernel() {
    int idx = blockIdx.x * blockDim.x + threadIdx.x;
    if (idx >= SEQ * 32) return;
    int s = idx >> 5;
    int j = idx & 31;
    // inv_freq = 10000^(-j/32)  (log2(10000)/32 = 0.41524101186092...)
    float invf = exp2f(-(float)j * 0.41524101186092f);
    float ang  = (float)s * invf;
    g_cos[idx] = (float)cos((double)ang);
    g_sin[idx] = (float)sin((double)ang);
}

// ---------------- QKV GEMM (64x64 tile, K-major transposed smem) + RoPE epilogue ----------------
// C[m, n] = sum_k x[m,k] * qkv[n,k];  n-tile == exactly one head of one of {Q,K,V}
__global__ __launch_bounds__(256) void qkv_rope_kernel(
    const float* __restrict__ x, const float* __restrict__ w)
{
    __shared__ float smem[64 * 68];          // mainloop: As(16x68)+Bs(16x68); epilogue: Cs(64x68)
    float* As = smem;                        // As[k][m], pad 68
    float* Bs = smem + 16 * 68;              // Bs[k][n], pad 68

    const int tid = threadIdx.x;
    const int tx  = tid & 15, ty = tid >> 4;
    const int tx4 = tx * 4,  ty4 = ty * 4;
    const int m0  = blockIdx.x * 64;
    const int nt  = blockIdx.y;              // 0..47
    const int n0  = nt * 64;

    const int lm = tid & 63;                 // row within tile
    const int lk = (tid >> 6) << 2;          // k offset {0,4,8,12}

    float acc[4][4];
#pragma unroll
    for (int i = 0; i < 4; ++i)
#pragma unroll
        for (int j = 0; j < 4; ++j) acc[i][j] = 0.f;

    for (int k0 = 0; k0 < DMODEL; k0 += 16) {
        float4 va = *(const float4*)&x[(size_t)(m0 + lm) * DMODEL + k0 + lk];
        float4 vb = *(const float4*)&w[(size_t)(n0 + lm) * DMODEL + k0 + lk];
        __syncthreads();
        As[(lk+0)*68 + lm] = va.x; As[(lk+1)*68 + lm] = va.y;
        As[(lk+2)*68 + lm] = va.z; As[(lk+3)*68 + lm] = va.w;
        Bs[(lk+0)*68 + lm] = vb.x; Bs[(lk+1)*68 + lm] = vb.y;
        Bs[(lk+2)*68 + lm] = vb.z; Bs[(lk+3)*68 + lm] = vb.w;
        __syncthreads();
#pragma unroll
        for (int k = 0; k < 16; ++k) {
            float4 a4 = *(const float4*)&As[k*68 + ty4];
            float4 b4 = *(const float4*)&Bs[k*68 + tx4];
            float a[4] = {a4.x, a4.y, a4.z, a4.w};
            float b[4] = {b4.x, b4.y, b4.z, b4.w};
#pragma unroll
            for (int i = 0; i < 4; ++i)
#pragma unroll
                for (int j = 0; j < 4; ++j)
                    acc[i][j] = fmaf(a[i], b[j], acc[i][j]);
        }
    }

    // Epilogue: stage tile to smem, apply RoPE (partner = d^32), write [B,H,S,64]
    __syncthreads();
    float* Cs = smem;                        // 64 x 68
#pragma unroll
    for (int i = 0; i < 4; ++i)
#pragma unroll
        for (int j = 0; j < 4; ++j)
            Cs[(ty4 + i)*68 + tx4 + j] = acc[i][j];
    __syncthreads();

    const int sel = nt >> 4;                 // 0=Q 1=K 2=V
    const int h   = nt & 15;
    float* dst = (sel == 0) ? g_q : ((sel == 1) ? g_k : g_v);

    for (int e = tid; e < 4096; e += 256) {
        int r = e >> 6, d = e & 63;
        int gm = m0 + r;
        int b  = gm >> 11;
        int s  = gm & 2047;
        float val = Cs[r*68 + d];
        if (sel < 2) {
            float part = Cs[r*68 + (d ^ 32)];
            int   j    = d & 31;
            float c  = g_cos[s*32 + j];
            float sn = g_sin[s*32 + j];
            float rot = (d < 32) ? -part : part;
            val = val * c + rot * sn;
        }
        dst[(((size_t)b*NH + h)*SEQ + s)*DHD + d] = val;
    }
}

// ---------------- Flash attention (causal), 64x64 tiles, fp32 ----------------
// grid: (32 q-tiles, 64 b*h);  256 threads as 16x16, 4x4 register tiles.
// P@V uses register-resident P broadcast via shfl (width=16) -> no P smem buffer.
__global__ __launch_bounds__(256) void attn_kernel()
{
    extern __shared__ float sm[];
    float* Qt = sm;                 // [64 d][68]  Qt[d][m] (Q pre-scaled by 1/8)
    float* Kt = sm + 64*68;         // [64 d][68]  Kt[d][c]
    float* Vs = sm + 2*64*68;       // [64 c][68]  Vs[c][d]

    const int tid = threadIdx.x;
    const int tx  = tid & 15, ty = tid >> 4;
    const int tx4 = tx * 4,  ty4 = ty * 4;
    const int qt  = blockIdx.x;
    const int bh  = blockIdx.y;

    const float* Qg = g_q + (size_t)bh * SEQ * DHD;
    const float* Kg = g_k + (size_t)bh * SEQ * DHD;
    const float* Vg = g_v + (size_t)bh * SEQ * DHD;

    // load Q tile transposed, fold in 1/sqrt(64)
    for (int i = tid; i < 1024; i += 256) {
        int m  = i >> 4;
        int d0 = (i & 15) << 2;
        float4 q = *(const float4*)&Qg[(size_t)(qt*64 + m)*DHD + d0];
        Qt[(d0+0)*68 + m] = q.x * 0.125f;
        Qt[(d0+1)*68 + m] = q.y * 0.125f;
        Qt[(d0+2)*68 + m] = q.z * 0.125f;
        Qt[(d0+3)*68 + m] = q.w * 0.125f;
    }

    float mi[4], li[4], o[4][4];
#pragma unroll
    for (int i = 0; i < 4; ++i) {
        mi[i] = -INFINITY; li[i] = 0.f;
#pragma unroll
        for (int j = 0; j < 4; ++j) o[i][j] = 0.f;
    }

    for (int kt = 0; kt <= qt; ++kt) {
        __syncthreads();                      // prior-iter Kt/Vs reads complete
        for (int i = tid; i < 1024; i += 256) {
            int c  = i >> 4;
            int d0 = (i & 15) << 2;
            float4 kv = *(const float4*)&Kg[(size_t)(kt*64 + c)*DHD + d0];
            Kt[(d0+0)*68 + c] = kv.x; Kt[(d0+1)*68 + c] = kv.y;
            Kt[(d0+2)*68 + c] = kv.z; Kt[(d0+3)*68 + c] = kv.w;
            float4 vv = *(const float4*)&Vg[(size_t)(kt*64 + c)*DHD + d0];
            *(float4*)&Vs[c*68 + d0] = vv;
        }
        __syncthreads();

        // S = (Q/8) K^T
        float sc[4][4];
#pragma unroll
        for (int i = 0; i < 4; ++i)
#pragma unroll
            for (int j = 0; j < 4; ++j) sc[i][j] = 0.f;
#pragma unroll 16
        for (int d = 0; d < 64; ++d) {
            float4 a4 = *(const float4*)&Qt[d*68 + ty4];
            float4 b4 = *(const float4*)&Kt[d*68 + tx4];
            float a[4] = {a4.x, a4.y, a4.z, a4.w};
            float b[4] = {b4.x, b4.y, b4.z, b4.w};
#pragma unroll
            for (int i = 0; i < 4; ++i)
#pragma unroll
                for (int j = 0; j < 4; ++j)
                    sc[i][j] = fmaf(a[i], b[j], sc[i][j]);
        }

        if (kt == qt) {                       // causal mask inside diagonal tile
#pragma unroll
            for (int i = 0; i < 4; ++i)
#pragma unroll
                for (int j = 0; j < 4; ++j)
                    if (tx4 + j > ty4 + i) sc[i][j] = -INFINITY;
        }

        // online softmax (row reductions across tx via shfl-xor; lanes: tx = low 4 bits)
        float pr[4][4];
#pragma unroll
        for (int i = 0; i < 4; ++i) {
            float v = fmaxf(fmaxf(sc[i][0], sc[i][1]), fmaxf(sc[i][2], sc[i][3]));
            v = fmaxf(v, __shfl_xor_sync(0xffffffffu, v, 1));
            v = fmaxf(v, __shfl_xor_sync(0xffffffffu, v, 2));
            v = fmaxf(v, __shfl_xor_sync(0xffffffffu, v, 4));
            v = fmaxf(v, __shfl_xor_sync(0xffffffffu, v, 8));
            float mn    = fmaxf(mi[i], v);
            float alpha = __expf(mi[i] - mn);
            mi[i] = mn;
            float rs = 0.f;
#pragma unroll
            for (int j = 0; j < 4; ++j) {
                pr[i][j] = __expf(sc[i][j] - mn);
                rs += pr[i][j];
            }
            rs += __shfl_xor_sync(0xffffffffu, rs, 1);
            rs += __shfl_xor_sync(0xffffffffu, rs, 2);
            rs += __shfl_xor_sync(0xffffffffu, rs, 4);
            rs += __shfl_xor_sync(0xffffffffu, rs, 8);
            li[i] = li[i] * alpha + rs;
#pragma unroll
            for (int j = 0; j < 4; ++j) o[i][j] *= alpha;
        }

        // O += P @ V : broadcast P[r][c] from owner lane (same ty, tx = c>>2)
        for (int cc = 0; cc < 16; ++cc) {
#pragma unroll
            for (int j2 = 0; j2 < 4; ++j2) {
                int c = cc * 4 + j2;
                float4 b4 = *(const float4*)&Vs[c*68 + tx4];
                float p0 = __shfl_sync(0xffffffffu, pr[0][j2], cc, 16);
                float p1 = __shfl_sync(0xffffffffu, pr[1][j2], cc, 16);
                float p2 = __shfl_sync(0xffffffffu, pr[2][j2], cc, 16);
                float p3 = __shfl_sync(0xffffffffu, pr[3][j2], cc, 16);
                o[0][0] = fmaf(p0, b4.x, o[0][0]); o[0][1] = fmaf(p0, b4.y, o[0][1]);
                o[0][2] = fmaf(p0, b4.z, o[0][2]); o[0][3] = fmaf(p0, b4.w, o[0][3]);
                o[1][0] = fmaf(p1, b4.x, o[1][0]); o[1][1] = fmaf(p1, b4.y, o[1][1]);
                o[1][2] = fmaf(p1, b4.z, o[1][2]); o[1][3] = fmaf(p1, b4.w, o[1][3]);
                o[2][0] = fmaf(p2, b4.x, o[2][0]); o[2][1] = fmaf(p2, b4.y, o[2][1]);
                o[2][2] = fmaf(p2, b4.z, o[2][2]); o[2][3] = fmaf(p2, b4.w, o[2][3]);
                o[3][0] = fmaf(p3, b4.x, o[3][0]); o[3][1] = fmaf(p3, b4.y, o[3][1]);
                o[3][2] = fmaf(p3, b4.z, o[3][2]); o[3][3] = fmaf(p3, b4.w, o[3][3]);
            }
        }
    }

    // write O (normalize by l) to [B, S, H*64 + d] so out-proj reads row-major
    const int b = bh >> 4, h = bh & 15;
#pragma unroll
    for (int i = 0; i < 4; ++i) {
        float inv = 1.0f / li[i];
        int s = qt*64 + ty4 + i;
        float4 r = make_float4(o[i][0]*inv, o[i][1]*inv, o[i][2]*inv, o[i][3]*inv);
        *(float4*)&g_ao[((size_t)b*SEQ + s)*DMODEL + h*DHD + tx4] = r;
    }
}

// ---------------- Output projection GEMM: out = AO @ wo^T ----------------
__global__ __launch_bounds__(256) void out_proj_kernel(
    const float* __restrict__ w, float* __restrict__ out)
{
    __shared__ float smem[2 * 16 * 68];
    float* As = smem;
    float* Bs = smem + 16 * 68;

    const int tid = threadIdx.x;
    const int tx  = tid & 15, ty = tid >> 4;
    const int tx4 = tx * 4,  ty4 = ty * 4;
    const int m0  = blockIdx.x * 64;
    const int n0  = blockIdx.y * 64;
    const int lm  = tid & 63;
    const int lk  = (tid >> 6) << 2;

    float acc[4][4];
#pragma unroll
    for (int i = 0; i < 4; ++i)
#pragma unroll
        for (int j = 0; j < 4; ++j) acc[i][j] = 0.f;

    for (int k0 = 0; k0 < DMODEL; k0 += 16) {
        float4 va = *(const float4*)&g_ao[(size_t)(m0 + lm) * DMODEL + k0 + lk];
        float4 vb = *(const float4*)&w[(size_t)(n0 + lm) * DMODEL + k0 + lk];
        __syncthreads();
        As[(lk+0)*68 + lm] = va.x; As[(lk+1)*68 + lm] = va.y;
        As[(lk+2)*68 + lm] = va.z; As[(lk+3)*68 + lm] = va.w;
        Bs[(lk+0)*68 + lm] = vb.x; Bs[(lk+1)*68 + lm] = vb.y;
        Bs[(lk+2)*68 + lm] = vb.z; Bs[(lk+3)*68 + lm] = vb.w;
        __syncthreads();
#pragma unroll
        for (int k = 0; k < 16; ++k) {
            float4 a4 = *(const float4*)&As[k*68 + ty4];
            float4 b4 = *(const float4*)&Bs[k*68 + tx4];
            float a[4] = {a4.x, a4.y, a4.z, a4.w};
            float b[4] = {b4.x, b4.y, b4.z, b4.w};
#pragma unroll
            for (int i = 0; i < 4; ++i)
#pragma unroll
                for (int j = 0; j < 4; ++j)
                    acc[i][j] = fmaf(a[i], b[j], acc[i][j]);
        }
    }

#pragma unroll
    for (int i = 0; i < 4; ++i) {
        int gm = m0 + ty4 + i;
        *(float4*)&out[(size_t)gm * DMODEL + n0 + tx4] =
            make_float4(acc[i][0], acc[i][1], acc[i][2], acc[i][3]);
    }
}

// ---------------- launch ----------------
extern "C" void kernel_launch(void* const* d_in, const int* in_sizes, int n_in,
                              void* d_out, int out_size)
{
    (void)in_sizes; (void)n_in; (void)out_size;
    const float* x    = (const float*)d_in[0];
    const float* qkvw = (const float*)d_in[1];
    const float* wo   = (const float*)d_in[2];
    float*       out  = (float*)d_out;

    rope_table_kernel<<<(SEQ*32 + 255)/256, 256>>>();
    qkv_rope_kernel<<<dim3(MTOT/64, N_QKV/64), 256>>>(x, qkvw);

    const int attn_smem = 3 * 64 * 68 * 4;   // 52224 B
    cudaFuncSetAttribute(attn_kernel, cudaFuncAttributeMaxDynamicSharedMemorySize, attn_smem);
    attn_kernel<<<dim3(SEQ/64, BATCH*NH), 256, attn_smem>>>();

    out_proj_kernel<<<dim3(MTOT/64, DMODEL/64), 256>>>(wo, out);
}

// round 7
// speedup vs baseline: 1.4726x; 1.4726x over previous
#include <cuda_runtime.h>
#include <math.h>
#include <stdint.h>

// Problem constants
#define BATCH 4
#define SEQ   2048
#define DMODEL 1024
#define NH    16
#define DHD   64
#define MTOT  (BATCH*SEQ)      // 8192
#define N_QKV (3*DMODEL)       // 3072

// ---------------- scratch (static device globals; no allocation) ----------------
__device__ __align__(16) float g_q [(size_t)BATCH*NH*SEQ*DHD];
__device__ __align__(16) float g_k [(size_t)BATCH*NH*SEQ*DHD];
__device__ __align__(16) float g_v [(size_t)BATCH*NH*SEQ*DHD];
__device__ __align__(16) float g_ao[(size_t)MTOT*DMODEL];
__device__ float g_cos[SEQ*32];
__device__ float g_sin[SEQ*32];

// ---------------- packed f32x2 helpers (FFMA2 is PTX-only; ptxas never auto-fuses) ----
static __device__ __forceinline__ unsigned long long pack2(float x, float y) {
    unsigned long long r;
    asm("mov.b64 %0, {%1, %2};" : "=l"(r) : "f"(x), "f"(y));
    return r;
}
static __device__ __forceinline__ void ffma2(unsigned long long& d,
                                             unsigned long long a,
                                             unsigned long long b) {
    asm("fma.rn.f32x2 %0, %1, %2, %3;" : "=l"(d) : "l"(a), "l"(b), "l"(d));
}
static __device__ __forceinline__ void unpack2(unsigned long long v, float& lo, float& hi) {
    asm("mov.b64 {%0, %1}, %2;" : "=f"(lo), "=f"(hi) : "l"(v));
}

// ---------------- RoPE tables ----------------
__global__ void rope_table_kernel() {
    int idx = blockIdx.x * blockDim.x + threadIdx.x;
    if (idx >= SEQ * 32) return;
    int s = idx >> 5;
    int j = idx & 31;
    float invf = exp2f(-(float)j * 0.41524101186092f);  // 10000^(-j/32)
    float ang  = (float)s * invf;
    g_cos[idx] = (float)cos((double)ang);
    g_sin[idx] = (float)sin((double)ang);
}

// ---------------- shared 128x128 GEMM mainloop (C = A * B^T, K = 1024) ----------------
// 256 threads; 8x8 per-thread tile via f32x2 (4 row-pairs x 8 cols).
// smem k-major, stride 132: STS conflict-free (16-row groups land on disjoint
// bank halves), LDS.128 conflict-free (b: 8-lane phase covers 32 banks; a: broadcast).
// Double buffered, one __syncthreads per K-chunk of 8.
__device__ __forceinline__ void gemm128(const float* __restrict__ A,
                                        const float* __restrict__ B,
                                        int m0, int n0,
                                        unsigned long long acc2[4][8])
{
    __shared__ __align__(16) float As[2 * 8 * 132];
    __shared__ __align__(16) float Bs[2 * 8 * 132];
    const int BUFS = 8 * 132;

    const int tid = threadIdx.x;
    const int row = tid >> 1;            // 0..127 (tile row to load)
    const int kq  = (tid & 1) * 4;       // k offset {0,4}
    const int tx  = tid & 15, ty = tid >> 4;
    const int tx4 = tx * 4,  ty4 = ty * 4;

    const float* Ag = A + (size_t)(m0 + row) * DMODEL + kq;
    const float* Bg = B + (size_t)(n0 + row) * DMODEL + kq;

    float4 ra = *(const float4*)Ag;
    float4 rb = *(const float4*)Bg;
    As[(kq+0)*132 + row] = ra.x; As[(kq+1)*132 + row] = ra.y;
    As[(kq+2)*132 + row] = ra.z; As[(kq+3)*132 + row] = ra.w;
    Bs[(kq+0)*132 + row] = rb.x; Bs[(kq+1)*132 + row] = rb.y;
    Bs[(kq+2)*132 + row] = rb.z; Bs[(kq+3)*132 + row] = rb.w;
    __syncthreads();

    int buf = 0;
    const int NITER = DMODEL / 8;        // 128
    for (int it = 0; it < NITER; ++it) {
        const bool has_next = (it + 1 < NITER);
        if (has_next) {                  // LDG early; hidden under compute
            ra = *(const float4*)(Ag + (it + 1) * 8);
            rb = *(const float4*)(Bg + (it + 1) * 8);
        }
        const float* a_s = As + buf * BUFS;
        const float* b_s = Bs + buf * BUFS;
#pragma unroll
        for (int k = 0; k < 8; ++k) {
            ulonglong2 av0 = *(const ulonglong2*)&a_s[k*132 + ty4];       // rows ty4+0..3
            ulonglong2 av1 = *(const ulonglong2*)&a_s[k*132 + 64 + ty4];  // rows 64+ty4+0..3
            float4 bv0 = *(const float4*)&b_s[k*132 + tx4];
            float4 bv1 = *(const float4*)&b_s[k*132 + 64 + tx4];
            unsigned long long ap[4] = { av0.x, av0.y, av1.x, av1.y };
            unsigned long long bb[8] = {
                pack2(bv0.x, bv0.x), pack2(bv0.y, bv0.y),
                pack2(bv0.z, bv0.z), pack2(bv0.w, bv0.w),
                pack2(bv1.x, bv1.x), pack2(bv1.y, bv1.y),
                pack2(bv1.z, bv1.z), pack2(bv1.w, bv1.w) };
#pragma unroll
            for (int ip = 0; ip < 4; ++ip)
#pragma unroll
                for (int j = 0; j < 8; ++j)
                    ffma2(acc2[ip][j], ap[ip], bb[j]);
        }
        if (has_next) {
            // write next chunk to the other buffer (its last readers synced at end
            // of previous iter), then sync so everyone sees it next iter
            float* ad = As + (buf ^ 1) * BUFS;
            float* bd = Bs + (buf ^ 1) * BUFS;
            ad[(kq+0)*132 + row] = ra.x; ad[(kq+1)*132 + row] = ra.y;
            ad[(kq+2)*132 + row] = ra.z; ad[(kq+3)*132 + row] = ra.w;
            bd[(kq+0)*132 + row] = rb.x; bd[(kq+1)*132 + row] = rb.y;
            bd[(kq+2)*132 + row] = rb.z; bd[(kq+3)*132 + row] = rb.w;
            __syncthreads();
        }
        buf ^= 1;
    }
}

// unpack acc2 -> acc[8][8]; row i: i<4 -> ty4+i, else 64+ty4+(i-4); col j: j<4 -> tx4+j, else 64+tx4+(j-4)
static __device__ __forceinline__ void unpack_acc(unsigned long long acc2[4][8], float acc[8][8]) {
#pragma unroll
    for (int ip = 0; ip < 4; ++ip)
#pragma unroll
        for (int j = 0; j < 8; ++j) {
            float lo, hi;
            unpack2(acc2[ip][j], lo, hi);
            int i0 = (ip < 2) ? (2*ip) : (4 + 2*(ip-2));
            acc[i0][j]   = lo;
            acc[i0+1][j] = hi;
        }
}

// ---------------- QKV GEMM + register-resident RoPE epilogue ----------------
// grid (64, 24): n-tile of 128 = two heads of one of {Q,K,V}. RoPE partner d^32
// lives on lane^8 (same warp, same ty) -> shfl_xor, no smem staging.
__global__ __launch_bounds__(256, 2) void qkv_rope_kernel(
    const float* __restrict__ x, const float* __restrict__ w)
{
    unsigned long long acc2[4][8];
#pragma unroll
    for (int ip = 0; ip < 4; ++ip)
#pragma unroll
        for (int j = 0; j < 8; ++j) acc2[ip][j] = 0ull;

    const int m0 = blockIdx.x * 128;
    const int nt = blockIdx.y;                // 0..23
    gemm128(x, w, m0, nt * 128, acc2);

    float acc[8][8];
    unpack_acc(acc2, acc);

    const int tid = threadIdx.x;
    const int tx  = tid & 15, ty = tid >> 4;
    const int tx4 = tx * 4,  ty4 = ty * 4;

    const int sel   = nt >> 3;                // 0=Q 1=K 2=V
    const int hbase = (nt & 7) * 2;
    float* dst = (sel == 0) ? g_q : ((sel == 1) ? g_k : g_v);
    const bool do_rope = (sel < 2);
    const int jjbase = (tx & 7) * 4;          // (d & 31) base for this thread's cols

#pragma unroll
    for (int i = 0; i < 8; ++i) {
        int rrow = (i < 4) ? (ty4 + i) : (64 + ty4 + (i - 4));
        int m = m0 + rrow;
        int b = m >> 11;
        int s = m & 2047;
        float outv[2][4];
#pragma unroll
        for (int sp = 0; sp < 2; ++sp) {
#pragma unroll
            for (int j = 0; j < 4; ++j) {
                float val  = acc[i][sp*4 + j];
                float part = __shfl_xor_sync(0xffffffffu, val, 8);  // col d^32 (uniform flow)
                if (do_rope) {
                    float rot = (tx & 8) ? part : -part;            // d<32 -> -x2, d>=32 -> +x1
                    int jj = jjbase + j;
                    float c  = g_cos[s*32 + jj];
                    float sn = g_sin[s*32 + jj];
                    val = val * c + rot * sn;
                }
                outv[sp][j] = val;
            }
        }
#pragma unroll
        for (int sp = 0; sp < 2; ++sp) {
            int h = hbase + sp;
            *(float4*)&dst[(((size_t)b*NH + h)*SEQ + s)*DHD + tx4] =
                make_float4(outv[sp][0], outv[sp][1], outv[sp][2], outv[sp][3]);
        }
    }
}

// ---------------- Flash attention (causal), 64x64 tiles, fp32 (unchanged this round) ----
__global__ __launch_bounds__(256) void attn_kernel()
{
    extern __shared__ float sm[];
    float* Qt = sm;                 // [64 d][68]  Qt[d][m] (Q pre-scaled by 1/8)
    float* Kt = sm + 64*68;         // [64 d][68]  Kt[d][c]
    float* Vs = sm + 2*64*68;       // [64 c][68]  Vs[c][d]

    const int tid = threadIdx.x;
    const int tx  = tid & 15, ty = tid >> 4;
    const int tx4 = tx * 4,  ty4 = ty * 4;
    const int qt  = blockIdx.x;
    const int bh  = blockIdx.y;

    const float* Qg = g_q + (size_t)bh * SEQ * DHD;
    const float* Kg = g_k + (size_t)bh * SEQ * DHD;
    const float* Vg = g_v + (size_t)bh * SEQ * DHD;

    for (int i = tid; i < 1024; i += 256) {
        int m  = i >> 4;
        int d0 = (i & 15) << 2;
        float4 q = *(const float4*)&Qg[(size_t)(qt*64 + m)*DHD + d0];
        Qt[(d0+0)*68 + m] = q.x * 0.125f;
        Qt[(d0+1)*68 + m] = q.y * 0.125f;
        Qt[(d0+2)*68 + m] = q.z * 0.125f;
        Qt[(d0+3)*68 + m] = q.w * 0.125f;
    }

    float mi[4], li[4], o[4][4];
#pragma unroll
    for (int i = 0; i < 4; ++i) {
        mi[i] = -INFINITY; li[i] = 0.f;
#pragma unroll
        for (int j = 0; j < 4; ++j) o[i][j] = 0.f;
    }

    for (int kt = 0; kt <= qt; ++kt) {
        __syncthreads();
        for (int i = tid; i < 1024; i += 256) {
            int c  = i >> 4;
            int d0 = (i & 15) << 2;
            float4 kv = *(const float4*)&Kg[(size_t)(kt*64 + c)*DHD + d0];
            Kt[(d0+0)*68 + c] = kv.x; Kt[(d0+1)*68 + c] = kv.y;
            Kt[(d0+2)*68 + c] = kv.z; Kt[(d0+3)*68 + c] = kv.w;
            float4 vv = *(const float4*)&Vg[(size_t)(kt*64 + c)*DHD + d0];
            *(float4*)&Vs[c*68 + d0] = vv;
        }
        __syncthreads();

        float sc[4][4];
#pragma unroll
        for (int i = 0; i < 4; ++i)
#pragma unroll
            for (int j = 0; j < 4; ++j) sc[i][j] = 0.f;
#pragma unroll 16
        for (int d = 0; d < 64; ++d) {
            float4 a4 = *(const float4*)&Qt[d*68 + ty4];
            float4 b4 = *(const float4*)&Kt[d*68 + tx4];
            float a[4] = {a4.x, a4.y, a4.z, a4.w};
            float b[4] = {b4.x, b4.y, b4.z, b4.w};
#pragma unroll
            for (int i = 0; i < 4; ++i)
#pragma unroll
                for (int j = 0; j < 4; ++j)
                    sc[i][j] = fmaf(a[i], b[j], sc[i][j]);
        }

        if (kt == qt) {
#pragma unroll
            for (int i = 0; i < 4; ++i)
#pragma unroll
                for (int j = 0; j < 4; ++j)
                    if (tx4 + j > ty4 + i) sc[i][j] = -INFINITY;
        }

        float pr[4][4];
#pragma unroll
        for (int i = 0; i < 4; ++i) {
            float v = fmaxf(fmaxf(sc[i][0], sc[i][1]), fmaxf(sc[i][2], sc[i][3]));
            v = fmaxf(v, __shfl_xor_sync(0xffffffffu, v, 1));
            v = fmaxf(v, __shfl_xor_sync(0xffffffffu, v, 2));
            v = fmaxf(v, __shfl_xor_sync(0xffffffffu, v, 4));
            v = fmaxf(v, __shfl_xor_sync(0xffffffffu, v, 8));
            float mn    = fmaxf(mi[i], v);
            float alpha = __expf(mi[i] - mn);
            mi[i] = mn;
            float rs = 0.f;
#pragma unroll
            for (int j = 0; j < 4; ++j) {
                pr[i][j] = __expf(sc[i][j] - mn);
                rs += pr[i][j];
            }
            rs += __shfl_xor_sync(0xffffffffu, rs, 1);
            rs += __shfl_xor_sync(0xffffffffu, rs, 2);
            rs += __shfl_xor_sync(0xffffffffu, rs, 4);
            rs += __shfl_xor_sync(0xffffffffu, rs, 8);
            li[i] = li[i] * alpha + rs;
#pragma unroll
            for (int j = 0; j < 4; ++j) o[i][j] *= alpha;
        }

        for (int cc = 0; cc < 16; ++cc) {
#pragma unroll
            for (int j2 = 0; j2 < 4; ++j2) {
                int c = cc * 4 + j2;
                float4 b4 = *(const float4*)&Vs[c*68 + tx4];
                float p0 = __shfl_sync(0xffffffffu, pr[0][j2], cc, 16);
                float p1 = __shfl_sync(0xffffffffu, pr[1][j2], cc, 16);
                float p2 = __shfl_sync(0xffffffffu, pr[2][j2], cc, 16);
                float p3 = __shfl_sync(0xffffffffu, pr[3][j2], cc, 16);
                o[0][0] = fmaf(p0, b4.x, o[0][0]); o[0][1] = fmaf(p0, b4.y, o[0][1]);
                o[0][2] = fmaf(p0, b4.z, o[0][2]); o[0][3] = fmaf(p0, b4.w, o[0][3]);
                o[1][0] = fmaf(p1, b4.x, o[1][0]); o[1][1] = fmaf(p1, b4.y, o[1][1]);
                o[1][2] = fmaf(p1, b4.z, o[1][2]); o[1][3] = fmaf(p1, b4.w, o[1][3]);
                o[2][0] = fmaf(p2, b4.x, o[2][0]); o[2][1] = fmaf(p2, b4.y, o[2][1]);
                o[2][2] = fmaf(p2, b4.z, o[2][2]); o[2][3] = fmaf(p2, b4.w, o[2][3]);
                o[3][0] = fmaf(p3, b4.x, o[3][0]); o[3][1] = fmaf(p3, b4.y, o[3][1]);
                o[3][2] = fmaf(p3, b4.z, o[3][2]); o[3][3] = fmaf(p3, b4.w, o[3][3]);
            }
        }
    }

    const int b = bh >> 4, h = bh & 15;
#pragma unroll
    for (int i = 0; i < 4; ++i) {
        float inv = 1.0f / li[i];
        int s = qt*64 + ty4 + i;
        float4 r = make_float4(o[i][0]*inv, o[i][1]*inv, o[i][2]*inv, o[i][3]*inv);
        *(float4*)&g_ao[((size_t)b*SEQ + s)*DMODEL + h*DHD + tx4] = r;
    }
}

// ---------------- Output projection: out = AO @ wo^T (128x128 f32x2 microkernel) ----------------
__global__ __launch_bounds__(256, 2) void out_proj_kernel(
    const float* __restrict__ w, float* __restrict__ out)
{
    unsigned long long acc2[4][8];
#pragma unroll
    for (int ip = 0; ip < 4; ++ip)
#pragma unroll
        for (int j = 0; j < 8; ++j) acc2[ip][j] = 0ull;

    const int m0 = blockIdx.x * 128;
    const int n0 = blockIdx.y * 128;
    gemm128(g_ao, w, m0, n0, acc2);

    float acc[8][8];
    unpack_acc(acc2, acc);

    const int tid = threadIdx.x;
    const int tx  = tid & 15, ty = tid >> 4;
    const int tx4 = tx * 4,  ty4 = ty * 4;

#pragma unroll
    for (int i = 0; i < 8; ++i) {
        int rrow = (i < 4) ? (ty4 + i) : (64 + ty4 + (i - 4));
        size_t base = (size_t)(m0 + rrow) * DMODEL + n0;
        *(float4*)&out[base + tx4] =
            make_float4(acc[i][0], acc[i][1], acc[i][2], acc[i][3]);
        *(float4*)&out[base + 64 + tx4] =
            make_float4(acc[i][4], acc[i][5], acc[i][6], acc[i][7]);
    }
}

// ---------------- launch ----------------
extern "C" void kernel_launch(void* const* d_in, const int* in_sizes, int n_in,
                              void* d_out, int out_size)
{
    (void)in_sizes; (void)n_in; (void)out_size;
    const float* x    = (const float*)d_in[0];
    const float* qkvw = (const float*)d_in[1];
    const float* wo   = (const float*)d_in[2];
    float*       out  = (float*)d_out;

    rope_table_kernel<<<(SEQ*32 + 255)/256, 256>>>();
    qkv_rope_kernel<<<dim3(MTOT/128, N_QKV/128), 256>>>(x, qkvw);

    const int attn_smem = 3 * 64 * 68 * 4;   // 52224 B
    cudaFuncSetAttribute(attn_kernel, cudaFuncAttributeMaxDynamicSharedMemorySize, attn_smem);
    attn_kernel<<<dim3(SEQ/64, BATCH*NH), 256, attn_smem>>>();

    out_proj_kernel<<<dim3(MTOT/128, DMODEL/128), 256>>>(wo, out);
}

// round 8
// speedup vs baseline: 1.5184x; 1.0311x over previous
#include <cuda_runtime.h>
#include <math.h>
#include <stdint.h>

// Problem constants
#define BATCH 4
#define SEQ   2048
#define DMODEL 1024
#define NH    16
#define DHD   64
#define MTOT  (BATCH*SEQ)      // 8192
#define N_QKV (3*DMODEL)       // 3072

// ---------------- scratch (static device globals; no allocation) ----------------
__device__ __align__(16) float g_q [(size_t)BATCH*NH*SEQ*DHD];
__device__ __align__(16) float g_k [(size_t)BATCH*NH*SEQ*DHD];
__device__ __align__(16) float g_v [(size_t)BATCH*NH*SEQ*DHD];
__device__ __align__(16) float g_ao[(size_t)MTOT*DMODEL];
__device__ float g_cos[SEQ*32];
__device__ float g_sin[SEQ*32];

// ---------------- packed f32x2 helpers (FFMA2 is PTX-only; ptxas never auto-fuses) ----
static __device__ __forceinline__ unsigned long long pack2(float x, float y) {
    unsigned long long r;
    asm("mov.b64 %0, {%1, %2};" : "=l"(r) : "f"(x), "f"(y));
    return r;
}
static __device__ __forceinline__ void ffma2(unsigned long long& d,
                                             unsigned long long a,
                                             unsigned long long b) {
    asm("fma.rn.f32x2 %0, %1, %2, %3;" : "=l"(d) : "l"(a), "l"(b), "l"(d));
}
static __device__ __forceinline__ void mul2(unsigned long long& d, unsigned long long a) {
    asm("mul.rn.f32x2 %0, %0, %1;" : "+l"(d) : "l"(a));
}
static __device__ __forceinline__ void unpack2(unsigned long long v, float& lo, float& hi) {
    asm("mov.b64 {%0, %1}, %2;" : "=f"(lo), "=f"(hi) : "l"(v));
}

// ---------------- RoPE tables ----------------
__global__ void rope_table_kernel() {
    int idx = blockIdx.x * blockDim.x + threadIdx.x;
    if (idx >= SEQ * 32) return;
    int s = idx >> 5;
    int j = idx & 31;
    float invf = exp2f(-(float)j * 0.41524101186092f);  // 10000^(-j/32)
    float ang  = (float)s * invf;
    g_cos[idx] = (float)cos((double)ang);
    g_sin[idx] = (float)sin((double)ang);
}

// ---------------- shared 128x128 GEMM mainloop (C = A * B^T, K = 1024) ----------------
__device__ __forceinline__ void gemm128(const float* __restrict__ A,
                                        const float* __restrict__ B,
                                        int m0, int n0,
                                        unsigned long long acc2[4][8])
{
    __shared__ __align__(16) float As[2 * 8 * 132];
    __shared__ __align__(16) float Bs[2 * 8 * 132];
    const int BUFS = 8 * 132;

    const int tid = threadIdx.x;
    const int row = tid >> 1;            // 0..127 (tile row to load)
    const int kq  = (tid & 1) * 4;       // k offset {0,4}
    const int tx  = tid & 15, ty = tid >> 4;
    const int tx4 = tx * 4,  ty4 = ty * 4;

    const float* Ag = A + (size_t)(m0 + row) * DMODEL + kq;
    const float* Bg = B + (size_t)(n0 + row) * DMODEL + kq;

    float4 ra = *(const float4*)Ag;
    float4 rb = *(const float4*)Bg;
    As[(kq+0)*132 + row] = ra.x; As[(kq+1)*132 + row] = ra.y;
    As[(kq+2)*132 + row] = ra.z; As[(kq+3)*132 + row] = ra.w;
    Bs[(kq+0)*132 + row] = rb.x; Bs[(kq+1)*132 + row] = rb.y;
    Bs[(kq+2)*132 + row] = rb.z; Bs[(kq+3)*132 + row] = rb.w;
    __syncthreads();

    int buf = 0;
    const int NITER = DMODEL / 8;        // 128
    for (int it = 0; it < NITER; ++it) {
        const bool has_next = (it + 1 < NITER);
        if (has_next) {
            ra = *(const float4*)(Ag + (it + 1) * 8);
            rb = *(const float4*)(Bg + (it + 1) * 8);
        }
        const float* a_s = As + buf * BUFS;
        const float* b_s = Bs + buf * BUFS;
#pragma unroll
        for (int k = 0; k < 8; ++k) {
            ulonglong2 av0 = *(const ulonglong2*)&a_s[k*132 + ty4];
            ulonglong2 av1 = *(const ulonglong2*)&a_s[k*132 + 64 + ty4];
            float4 bv0 = *(const float4*)&b_s[k*132 + tx4];
            float4 bv1 = *(const float4*)&b_s[k*132 + 64 + tx4];
            unsigned long long ap[4] = { av0.x, av0.y, av1.x, av1.y };
            unsigned long long bb[8] = {
                pack2(bv0.x, bv0.x), pack2(bv0.y, bv0.y),
                pack2(bv0.z, bv0.z), pack2(bv0.w, bv0.w),
                pack2(bv1.x, bv1.x), pack2(bv1.y, bv1.y),
                pack2(bv1.z, bv1.z), pack2(bv1.w, bv1.w) };
#pragma unroll
            for (int ip = 0; ip < 4; ++ip)
#pragma unroll
                for (int j = 0; j < 8; ++j)
                    ffma2(acc2[ip][j], ap[ip], bb[j]);
        }
        if (has_next) {
            float* ad = As + (buf ^ 1) * BUFS;
            float* bd = Bs + (buf ^ 1) * BUFS;
            ad[(kq+0)*132 + row] = ra.x; ad[(kq+1)*132 + row] = ra.y;
            ad[(kq+2)*132 + row] = ra.z; ad[(kq+3)*132 + row] = ra.w;
            bd[(kq+0)*132 + row] = rb.x; bd[(kq+1)*132 + row] = rb.y;
            bd[(kq+2)*132 + row] = rb.z; bd[(kq+3)*132 + row] = rb.w;
            __syncthreads();
        }
        buf ^= 1;
    }
}

static __device__ __forceinline__ void unpack_acc(unsigned long long acc2[4][8], float acc[8][8]) {
#pragma unroll
    for (int ip = 0; ip < 4; ++ip)
#pragma unroll
        for (int j = 0; j < 8; ++j) {
            float lo, hi;
            unpack2(acc2[ip][j], lo, hi);
            int i0 = (ip < 2) ? (2*ip) : (4 + 2*(ip-2));
            acc[i0][j]   = lo;
            acc[i0+1][j] = hi;
        }
}

// ---------------- QKV GEMM + register-resident RoPE epilogue ----------------
__global__ __launch_bounds__(256, 2) void qkv_rope_kernel(
    const float* __restrict__ x, const float* __restrict__ w)
{
    unsigned long long acc2[4][8];
#pragma unroll
    for (int ip = 0; ip < 4; ++ip)
#pragma unroll
        for (int j = 0; j < 8; ++j) acc2[ip][j] = 0ull;

    const int m0 = blockIdx.x * 128;
    const int nt = blockIdx.y;                // 0..23
    gemm128(x, w, m0, nt * 128, acc2);

    float acc[8][8];
    unpack_acc(acc2, acc);

    const int tid = threadIdx.x;
    const int tx  = tid & 15, ty = tid >> 4;
    const int tx4 = tx * 4,  ty4 = ty * 4;

    const int sel   = nt >> 3;                // 0=Q 1=K 2=V
    const int hbase = (nt & 7) * 2;
    float* dst = (sel == 0) ? g_q : ((sel == 1) ? g_k : g_v);
    const bool do_rope = (sel < 2);
    const int jjbase = (tx & 7) * 4;

#pragma unroll
    for (int i = 0; i < 8; ++i) {
        int rrow = (i < 4) ? (ty4 + i) : (64 + ty4 + (i - 4));
        int m = m0 + rrow;
        int b = m >> 11;
        int s = m & 2047;
        float outv[2][4];
#pragma unroll
        for (int sp = 0; sp < 2; ++sp) {
#pragma unroll
            for (int j = 0; j < 4; ++j) {
                float val  = acc[i][sp*4 + j];
                float part = __shfl_xor_sync(0xffffffffu, val, 8);
                if (do_rope) {
                    float rot = (tx & 8) ? part : -part;
                    int jj = jjbase + j;
                    float c  = g_cos[s*32 + jj];
                    float sn = g_sin[s*32 + jj];
                    val = val * c + rot * sn;
                }
                outv[sp][j] = val;
            }
        }
#pragma unroll
        for (int sp = 0; sp < 2; ++sp) {
            int h = hbase + sp;
            *(float4*)&dst[(((size_t)b*NH + h)*SEQ + s)*DHD + tx4] =
                make_float4(outv[sp][0], outv[sp][1], outv[sp][2], outv[sp][3]);
        }
    }
}

// ---------------- Flash attention (causal), 64x64 tiles, packed f32x2 ----------------
// Both GEMMs (S = QK^T and O += P V) run on fma.rn.f32x2 with pairs along the
// q-row dimension. P@V reads a transposed P tile staged through smem (Ps[c][m]);
// no shfl broadcast. O accumulators stay packed; alpha rescale via mul.rn.f32x2.
__global__ __launch_bounds__(256, 2) void attn_kernel()
{
    extern __shared__ float sm[];
    float* Qt = sm;                 // [64 d][68]  Qt[d][m]  (Q/8)
    float* Kt = sm + 64*68;         // [64 d][68]  Kt[d][c]
    float* Vs = sm + 2*64*68;       // [64 c][68]  Vs[c][d]
    float* Ps = sm + 3*64*68;       // [64 c][68]  Ps[c][m]

    const int tid = threadIdx.x;
    const int tx  = tid & 15, ty = tid >> 4;
    const int tx4 = tx * 4,  ty4 = ty * 4;
    const int qt  = blockIdx.x;
    const int bh  = blockIdx.y;

    const float* Qg = g_q + (size_t)bh * SEQ * DHD;
    const float* Kg = g_k + (size_t)bh * SEQ * DHD;
    const float* Vg = g_v + (size_t)bh * SEQ * DHD;

    // load Q tile transposed, fold in 1/sqrt(64)
    for (int i = tid; i < 1024; i += 256) {
        int m  = i >> 4;
        int d0 = (i & 15) << 2;
        float4 q = *(const float4*)&Qg[(size_t)(qt*64 + m)*DHD + d0];
        Qt[(d0+0)*68 + m] = q.x * 0.125f;
        Qt[(d0+1)*68 + m] = q.y * 0.125f;
        Qt[(d0+2)*68 + m] = q.z * 0.125f;
        Qt[(d0+3)*68 + m] = q.w * 0.125f;
    }

    float mi[4], li[4];
    unsigned long long accO[2][4];          // O rows pairs (ty4+2p, ty4+2p+1) x dims tx4+j
#pragma unroll
    for (int i = 0; i < 4; ++i) { mi[i] = -INFINITY; li[i] = 0.f; }
#pragma unroll
    for (int p = 0; p < 2; ++p)
#pragma unroll
        for (int j = 0; j < 4; ++j) accO[p][j] = 0ull;

    for (int kt = 0; kt <= qt; ++kt) {
        __syncthreads();                     // prior-iter Kt/Vs/Ps reads complete (Qt ready on it 0)
        for (int i = tid; i < 1024; i += 256) {
            int c  = i >> 4;
            int d0 = (i & 15) << 2;
            float4 kv = *(const float4*)&Kg[(size_t)(kt*64 + c)*DHD + d0];
            Kt[(d0+0)*68 + c] = kv.x; Kt[(d0+1)*68 + c] = kv.y;
            Kt[(d0+2)*68 + c] = kv.z; Kt[(d0+3)*68 + c] = kv.w;
            float4 vv = *(const float4*)&Vg[(size_t)(kt*64 + c)*DHD + d0];
            *(float4*)&Vs[c*68 + d0] = vv;
        }
        __syncthreads();

        // S = (Q/8) K^T  — packed: pairs along q-rows, K broadcast-packed
        unsigned long long accS[2][4];
#pragma unroll
        for (int p = 0; p < 2; ++p)
#pragma unroll
            for (int j = 0; j < 4; ++j) accS[p][j] = 0ull;
#pragma unroll 8
        for (int d = 0; d < 64; ++d) {
            ulonglong2 ap = *(const ulonglong2*)&Qt[d*68 + ty4];
            float4 bv = *(const float4*)&Kt[d*68 + tx4];
            unsigned long long b0 = pack2(bv.x, bv.x);
            unsigned long long b1 = pack2(bv.y, bv.y);
            unsigned long long b2 = pack2(bv.z, bv.z);
            unsigned long long b3 = pack2(bv.w, bv.w);
            ffma2(accS[0][0], ap.x, b0); ffma2(accS[0][1], ap.x, b1);
            ffma2(accS[0][2], ap.x, b2); ffma2(accS[0][3], ap.x, b3);
            ffma2(accS[1][0], ap.y, b0); ffma2(accS[1][1], ap.y, b1);
            ffma2(accS[1][2], ap.y, b2); ffma2(accS[1][3], ap.y, b3);
        }

        float sc[4][4];
#pragma unroll
        for (int p = 0; p < 2; ++p)
#pragma unroll
            for (int j = 0; j < 4; ++j)
                unpack2(accS[p][j], sc[2*p][j], sc[2*p+1][j]);

        if (kt == qt) {                      // causal mask inside diagonal tile
#pragma unroll
            for (int i = 0; i < 4; ++i)
#pragma unroll
                for (int j = 0; j < 4; ++j)
                    if (tx4 + j > ty4 + i) sc[i][j] = -INFINITY;
        }

        // online softmax (row reductions across tx via shfl-xor; tx = low 4 lane bits)
        float pr[4][4], alpha[4];
#pragma unroll
        for (int i = 0; i < 4; ++i) {
            float v = fmaxf(fmaxf(sc[i][0], sc[i][1]), fmaxf(sc[i][2], sc[i][3]));
            v = fmaxf(v, __shfl_xor_sync(0xffffffffu, v, 1));
            v = fmaxf(v, __shfl_xor_sync(0xffffffffu, v, 2));
            v = fmaxf(v, __shfl_xor_sync(0xffffffffu, v, 4));
            v = fmaxf(v, __shfl_xor_sync(0xffffffffu, v, 8));
            float mn = fmaxf(mi[i], v);
            alpha[i] = __expf(mi[i] - mn);
            mi[i] = mn;
            float rs = 0.f;
#pragma unroll
            for (int j = 0; j < 4; ++j) {
                pr[i][j] = __expf(sc[i][j] - mn);
                rs += pr[i][j];
            }
            rs += __shfl_xor_sync(0xffffffffu, rs, 1);
            rs += __shfl_xor_sync(0xffffffffu, rs, 2);
            rs += __shfl_xor_sync(0xffffffffu, rs, 4);
            rs += __shfl_xor_sync(0xffffffffu, rs, 8);
            li[i] = li[i] * alpha[i] + rs;
        }

        // rescale packed O accumulators by per-row alpha pairs
        {
            unsigned long long al0 = pack2(alpha[0], alpha[1]);
            unsigned long long al1 = pack2(alpha[2], alpha[3]);
#pragma unroll
            for (int j = 0; j < 4; ++j) { mul2(accO[0][j], al0); mul2(accO[1][j], al1); }
        }

        // stage P transposed: Ps[c][m], m contiguous -> 4x STS.128
#pragma unroll
        for (int j = 0; j < 4; ++j)
            *(float4*)&Ps[(tx4 + j)*68 + ty4] =
                make_float4(pr[0][j], pr[1][j], pr[2][j], pr[3][j]);
        __syncthreads();

        // O += P @ V  — packed: pairs along q-rows from Ps, V broadcast-packed
#pragma unroll 8
        for (int c = 0; c < 64; ++c) {
            ulonglong2 ap = *(const ulonglong2*)&Ps[c*68 + ty4];
            float4 bv = *(const float4*)&Vs[c*68 + tx4];
            unsigned long long b0 = pack2(bv.x, bv.x);
            unsigned long long b1 = pack2(bv.y, bv.y);
            unsigned long long b2 = pack2(bv.z, bv.z);
            unsigned long long b3 = pack2(bv.w, bv.w);
            ffma2(accO[0][0], ap.x, b0); ffma2(accO[0][1], ap.x, b1);
            ffma2(accO[0][2], ap.x, b2); ffma2(accO[0][3], ap.x, b3);
            ffma2(accO[1][0], ap.y, b0); ffma2(accO[1][1], ap.y, b1);
            ffma2(accO[1][2], ap.y, b2); ffma2(accO[1][3], ap.y, b3);
        }
    }

    // write O (normalize by l) to [B, S, H*64 + d]
    const int b = bh >> 4, h = bh & 15;
    float o[4][4];
#pragma unroll
    for (int p = 0; p < 2; ++p)
#pragma unroll
        for (int j = 0; j < 4; ++j)
            unpack2(accO[p][j], o[2*p][j], o[2*p+1][j]);
#pragma unroll
    for (int i = 0; i < 4; ++i) {
        float inv = 1.0f / li[i];
        int s = qt*64 + ty4 + i;
        float4 r = make_float4(o[i][0]*inv, o[i][1]*inv, o[i][2]*inv, o[i][3]*inv);
        *(float4*)&g_ao[((size_t)b*SEQ + s)*DMODEL + h*DHD + tx4] = r;
    }
}

// ---------------- Output projection: out = AO @ wo^T (128x128 f32x2 microkernel) ----------------
__global__ __launch_bounds__(256, 2) void out_proj_kernel(
    const float* __restrict__ w, float* __restrict__ out)
{
    unsigned long long acc2[4][8];
#pragma unroll
    for (int ip = 0; ip < 4; ++ip)
#pragma unroll
        for (int j = 0; j < 8; ++j) acc2[ip][j] = 0ull;

    const int m0 = blockIdx.x * 128;
    const int n0 = blockIdx.y * 128;
    gemm128(g_ao, w, m0, n0, acc2);

    float acc[8][8];
    unpack_acc(acc2, acc);

    const int tid = threadIdx.x;
    const int tx  = tid & 15, ty = tid >> 4;
    const int tx4 = tx * 4,  ty4 = ty * 4;

#pragma unroll
    for (int i = 0; i < 8; ++i) {
        int rrow = (i < 4) ? (ty4 + i) : (64 + ty4 + (i - 4));
        size_t base = (size_t)(m0 + rrow) * DMODEL + n0;
        *(float4*)&out[base + tx4] =
            make_float4(acc[i][0], acc[i][1], acc[i][2], acc[i][3]);
        *(float4*)&out[base + 64 + tx4] =
            make_float4(acc[i][4], acc[i][5], acc[i][6], acc[i][7]);
    }
}

// ---------------- launch ----------------
extern "C" void kernel_launch(void* const* d_in, const int* in_sizes, int n_in,
                              void* d_out, int out_size)
{
    (void)in_sizes; (void)n_in; (void)out_size;
    const float* x    = (const float*)d_in[0];
    const float* qkvw = (const float*)d_in[1];
    const float* wo   = (const float*)d_in[2];
    float*       out  = (float*)d_out;

    rope_table_kernel<<<(SEQ*32 + 255)/256, 256>>>();
    qkv_rope_kernel<<<dim3(MTOT/128, N_QKV/128), 256>>>(x, qkvw);

    const int attn_smem = 4 * 64 * 68 * 4;   // 69632 B
    cudaFuncSetAttribute(attn_kernel, cudaFuncAttributeMaxDynamicSharedMemorySize, attn_smem);
    attn_kernel<<<dim3(SEQ/64, BATCH*NH), 256, attn_smem>>>();

    out_proj_kernel<<<dim3(MTOT/128, DMODEL/128), 256>>>(wo, out);
}

// round 12
// speedup vs baseline: 1.7593x; 1.1587x over previous
#include <cuda_runtime.h>
#include <cuda_bf16.h>
#include <math.h>
#include <stdint.h>

// Problem constants
#define BATCH 4
#define SEQ   2048
#define DMODEL 1024
#define NH    16
#define DHD   64
#define MTOT  (BATCH*SEQ)      // 8192
#define N_QKV (3*DMODEL)       // 3072

typedef unsigned short u16;
typedef unsigned int   u32;

// single dynamic-smem declaration shared by all kernels
extern __shared__ char dynsm[];

// ---------------- scratch (static device globals; no allocation) ----------------
__device__ __align__(16) float g_q [(size_t)BATCH*NH*SEQ*DHD];
__device__ __align__(16) float g_k [(size_t)BATCH*NH*SEQ*DHD];
__device__ __align__(16) float g_v [(size_t)BATCH*NH*SEQ*DHD];
__device__ __align__(16) u16 g_xh [(size_t)MTOT*DMODEL];
__device__ __align__(16) u16 g_xl [(size_t)MTOT*DMODEL];
__device__ __align__(16) u16 g_wh [(size_t)N_QKV*DMODEL];
__device__ __align__(16) u16 g_wl [(size_t)N_QKV*DMODEL];
__device__ __align__(16) u16 g_woh[(size_t)DMODEL*DMODEL];
__device__ __align__(16) u16 g_wol[(size_t)DMODEL*DMODEL];
__device__ __align__(16) u16 g_aoh[(size_t)MTOT*DMODEL];
__device__ __align__(16) u16 g_aol[(size_t)MTOT*DMODEL];
__device__ float g_cos[SEQ*32];
__device__ float g_sin[SEQ*32];

// ---------------- helpers ----------------
static __device__ __forceinline__ uint32_t smem_u32(const void* p) {
    uint32_t a;
    asm("{ .reg .u64 t; cvta.to.shared.u64 t, %1; cvt.u32.u64 %0, t; }" : "=r"(a) : "l"(p));
    return a;
}
// bf16 hi/lo split: x = hi + lo + O(2^-18 x)
static __device__ __forceinline__ void split1(float x, u16& h, u16& l) {
    __nv_bfloat16 hb = __float2bfloat16_rn(x);
    float hf = __bfloat162float(hb);
    __nv_bfloat16 lb = __float2bfloat16_rn(x - hf);
    h = __bfloat16_as_ushort(hb);
    l = __bfloat16_as_ushort(lb);
}
static __device__ __forceinline__ void ldmx4(uint32_t* r, uint32_t a) {
    asm volatile("ldmatrix.sync.aligned.m8n8.x4.shared.b16 {%0,%1,%2,%3}, [%4];"
        : "=r"(r[0]), "=r"(r[1]), "=r"(r[2]), "=r"(r[3]) : "r"(a));
}
static __device__ __forceinline__ void mma_bf16(float* c, const uint32_t* a, const uint32_t* b) {
    asm volatile("mma.sync.aligned.m16n8k16.row.col.f32.bf16.bf16.f32 "
        "{%0,%1,%2,%3}, {%4,%5,%6,%7}, {%8,%9}, {%0,%1,%2,%3};"
        : "+f"(c[0]), "+f"(c[1]), "+f"(c[2]), "+f"(c[3])
        : "r"(a[0]), "r"(a[1]), "r"(a[2]), "r"(a[3]), "r"(b[0]), "r"(b[1]));
}
// packed f32x2 (attention)
static __device__ __forceinline__ unsigned long long pack2(float x, float y) {
    unsigned long long r;
    asm("mov.b64 %0, {%1, %2};" : "=l"(r) : "f"(x), "f"(y));
    return r;
}
static __device__ __forceinline__ void ffma2(unsigned long long& d,
                                             unsigned long long a,
                                             unsigned long long b) {
    asm("fma.rn.f32x2 %0, %1, %2, %3;" : "=l"(d) : "l"(a), "l"(b), "l"(d));
}
static __device__ __forceinline__ void mul2(unsigned long long& d, unsigned long long a) {
    asm("mul.rn.f32x2 %0, %0, %1;" : "+l"(d) : "l"(a));
}
static __device__ __forceinline__ void unpack2(unsigned long long v, float& lo, float& hi) {
    asm("mov.b64 {%0, %1}, %2;" : "=f"(lo), "=f"(hi) : "l"(v));
}

// ---------------- RoPE tables ----------------
__global__ void rope_table_kernel() {
    int idx = blockIdx.x * blockDim.x + threadIdx.x;
    if (idx >= SEQ * 32) return;
    int s = idx >> 5;
    int j = idx & 31;
    float invf = exp2f(-(float)j * 0.41524101186092f);  // 10000^(-j/32)
    float ang  = (float)s * invf;
    g_cos[idx] = (float)cos((double)ang);
    g_sin[idx] = (float)sin((double)ang);
}

// ---------------- bf16 hi/lo pre-split kernels ----------------
static __device__ __forceinline__ void cvt_body(const float* __restrict__ src,
                                                u16* __restrict__ dh, u16* __restrict__ dl, int n4) {
    int i = blockIdx.x * blockDim.x + threadIdx.x;
    if (i >= n4) return;
    float4 v = ((const float4*)src)[i];
    u16 h0,h1,h2,h3,l0,l1,l2,l3;
    split1(v.x,h0,l0); split1(v.y,h1,l1); split1(v.z,h2,l2); split1(v.w,h3,l3);
    ((uint2*)dh)[i] = make_uint2((u32)h0 | ((u32)h1<<16), (u32)h2 | ((u32)h3<<16));
    ((uint2*)dl)[i] = make_uint2((u32)l0 | ((u32)l1<<16), (u32)l2 | ((u32)l3<<16));
}
__global__ void cvt_x_kernel (const float* __restrict__ s){ cvt_body(s, g_xh,  g_xl,  MTOT*DMODEL/4); }
__global__ void cvt_w_kernel (const float* __restrict__ s){ cvt_body(s, g_wh,  g_wl,  N_QKV*DMODEL/4); }
__global__ void cvt_wo_kernel(const float* __restrict__ s){ cvt_body(s, g_woh, g_wol, DMODEL*DMODEL/4); }

// ============================================================================
// bf16-split mma.sync GEMM: C[128,128] = A[m0:,K] * B[n0:,K]^T, K=1024.
// 256 thr = 8 warps (2m x 4n), warp tile 64x32, k-chunk 32, double buffered.
// smem buffer (40960B): Ah[128][40] bf16 @0, Al @10240, Bh @20480, Bl @30720.
// Row stride 80B: ldmatrix 8-row phases and STS phases bank-conflict-free
// (banks 20*r mod 32 distinct for r=0..7).
// ============================================================================
#define MM_BUF  40960
#define MM_SMEM 81920

__device__ __forceinline__ void mma_mainloop(
    const u16* __restrict__ Ah, const u16* __restrict__ Al,
    const u16* __restrict__ Bh, const u16* __restrict__ Bl,
    int m0, int n0, char* sm, uint32_t smb, float c[4][4][4])
{
    const int tid  = threadIdx.x;
    const int lane = tid & 31;
    const int wid  = tid >> 5;
    const int wm   = wid >> 2;       // 0..1
    const int wn   = wid & 3;        // 0..3
    const int r    = tid & 127;

    // global row pointers (warps 0-3 load A rows, warps 4-7 load B rows)
    const uint4* gh;
    const uint4* gl;
    int sregion;
    if (tid < 128) {
        gh = (const uint4*)(Ah + (size_t)(m0 + r) * DMODEL);
        gl = (const uint4*)(Al + (size_t)(m0 + r) * DMODEL);
        sregion = 0;
    } else {
        gh = (const uint4*)(Bh + (size_t)(n0 + r) * DMODEL);
        gl = (const uint4*)(Bl + (size_t)(n0 + r) * DMODEL);
        sregion = 20480;
    }
    char* sdh_row = sm + sregion + r * 80;
    char* sdl_row = sdh_row + 10240;

    // preload + store chunk 0
    uint4 vh[4], vl[4];
#pragma unroll
    for (int i = 0; i < 4; ++i) { vh[i] = gh[i]; vl[i] = gl[i]; }
#pragma unroll
    for (int i = 0; i < 4; ++i) {
        *(uint4*)(sdh_row + i*16) = vh[i];
        *(uint4*)(sdl_row + i*16) = vl[i];
    }
    __syncthreads();

    // ldmatrix per-lane addressing
    const int arow = (lane & 7) + ((lane >> 3) & 1) * 8;
    const int acol = (lane >> 4) * 16;
    const int brow = (lane & 7) + ((lane >> 4) & 1) * 8;
    const int bcol = ((lane >> 3) & 1) * 16;
    const uint32_t aBase = smb + (uint32_t)((wm*64 + arow) * 80 + acol);           // + buf + mt*1280 + s*32 (+10240 lo)
    const uint32_t bBase = smb + 20480 + (uint32_t)((wn*32 + brow) * 80 + bcol);   // + buf + p*1280 + s*32 (+10240 lo)

    int buf = 0;
    for (int ch = 0; ch < 32; ++ch) {
        const bool nxt = (ch + 1 < 32);
        if (nxt) {
#pragma unroll
            for (int i = 0; i < 4; ++i) {
                vh[i] = gh[(ch+1)*4 + i];
                vl[i] = gl[(ch+1)*4 + i];
            }
        }
        const uint32_t bo = (uint32_t)(buf * MM_BUF);
#pragma unroll
        for (int s = 0; s < 2; ++s) {
            uint32_t ah[4][4], al[4][4], bh[4][2], bl[4][2];
#pragma unroll
            for (int mt = 0; mt < 4; ++mt) {
                ldmx4(ah[mt], aBase + bo + mt*1280 + s*32);
                ldmx4(al[mt], aBase + bo + mt*1280 + s*32 + 10240);
            }
#pragma unroll
            for (int p = 0; p < 2; ++p) {
                uint32_t t4[4];
                ldmx4(t4, bBase + bo + p*1280 + s*32);
                bh[2*p][0] = t4[0]; bh[2*p][1] = t4[1];
                bh[2*p+1][0] = t4[2]; bh[2*p+1][1] = t4[3];
                ldmx4(t4, bBase + bo + p*1280 + s*32 + 10240);
                bl[2*p][0] = t4[0]; bl[2*p][1] = t4[1];
                bl[2*p+1][0] = t4[2]; bl[2*p+1][1] = t4[3];
            }
#pragma unroll
            for (int mt = 0; mt < 4; ++mt)
#pragma unroll
                for (int nt = 0; nt < 4; ++nt) {
                    mma_bf16(c[mt][nt], ah[mt], bh[nt]);
                    mma_bf16(c[mt][nt], ah[mt], bl[nt]);
                    mma_bf16(c[mt][nt], al[mt], bh[nt]);
                }
        }
        if (nxt) {
            char* dh = sdh_row + ((buf ^ 1) * MM_BUF);
            char* dl = sdl_row + ((buf ^ 1) * MM_BUF);
#pragma unroll
            for (int i = 0; i < 4; ++i) {
                *(uint4*)(dh + i*16) = vh[i];
                *(uint4*)(dl + i*16) = vl[i];
            }
            __syncthreads();
        }
        buf ^= 1;
    }
    __syncthreads();   // before smem reuse as Cs
}

// store fragments to Cs[128][132]
__device__ __forceinline__ void frag_to_cs(float* Cs, float c[4][4][4]) {
    const int tid = threadIdx.x;
    const int lane = tid & 31;
    const int wid = tid >> 5;
    const int wm = wid >> 2, wn = wid & 3;
    const int tr = lane >> 2, tc = (lane & 3) * 2;
#pragma unroll
    for (int mt = 0; mt < 4; ++mt)
#pragma unroll
        for (int nt = 0; nt < 4; ++nt) {
            int rr = wm*64 + mt*16 + tr;
            int cc = wn*32 + nt*8 + tc;
            *(float2*)&Cs[rr*132 + cc]       = make_float2(c[mt][nt][0], c[mt][nt][1]);
            *(float2*)&Cs[(rr+8)*132 + cc]   = make_float2(c[mt][nt][2], c[mt][nt][3]);
        }
    __syncthreads();
}

// ---------------- QKV GEMM (mma.sync) + RoPE epilogue ----------------
__global__ __launch_bounds__(256, 1) void qkv_mma_kernel()
{
    char* sm = dynsm;
    uint32_t smb = smem_u32(sm);

    float c[4][4][4];
#pragma unroll
    for (int a = 0; a < 4; ++a)
#pragma unroll
        for (int b = 0; b < 4; ++b)
#pragma unroll
            for (int d = 0; d < 4; ++d) c[a][b][d] = 0.f;

    const int m0 = blockIdx.x * 128;
    const int nt = blockIdx.y;                  // 0..23
    mma_mainloop(g_xh, g_xl, g_wh, g_wl, m0, nt * 128, sm, smb, c);

    float* Cs = (float*)sm;
    frag_to_cs(Cs, c);

    const int tid = threadIdx.x;
    const int sel   = nt >> 3;                  // 0=Q 1=K 2=V
    const int hbase = (nt & 7) * 2;
    float* dst = (sel == 0) ? g_q : ((sel == 1) ? g_k : g_v);

    for (int e = tid; e < 8192; e += 256) {
        int rr = e >> 6;
        int d  = (e & 63) * 2;                  // even col 0..126
        int m = m0 + rr;
        int b = m >> 11, s = m & 2047;
        float2 v = *(float2*)&Cs[rr*132 + d];
        int head = hbase + (d >> 6);
        int dloc = d & 63;
        if (sel < 2) {
            float2 p = *(float2*)&Cs[rr*132 + (d ^ 32)];
            int j = d & 31;
            float c0 = g_cos[s*32 + j],   c1 = g_cos[s*32 + j + 1];
            float s0 = g_sin[s*32 + j],   s1 = g_sin[s*32 + j + 1];
            if (dloc < 32) { v.x = v.x*c0 - p.x*s0; v.y = v.y*c1 - p.y*s1; }
            else           { v.x = v.x*c0 + p.x*s0; v.y = v.y*c1 + p.y*s1; }
        }
        *(float2*)&dst[(((size_t)b*NH + head)*SEQ + s)*DHD + dloc] = v;
    }
}

// ---------------- out_proj (mma.sync): out = AO @ wo^T ----------------
__global__ __launch_bounds__(256, 1) void out_proj_mma_kernel(float* __restrict__ out)
{
    char* sm = dynsm;
    uint32_t smb = smem_u32(sm);

    float c[4][4][4];
#pragma unroll
    for (int a = 0; a < 4; ++a)
#pragma unroll
        for (int b = 0; b < 4; ++b)
#pragma unroll
            for (int d = 0; d < 4; ++d) c[a][b][d] = 0.f;

    const int m0 = blockIdx.x * 128;
    const int n0 = blockIdx.y * 128;
    mma_mainloop(g_aoh, g_aol, g_woh, g_wol, m0, n0, sm, smb, c);

    float* Cs = (float*)sm;
    frag_to_cs(Cs, c);

    const int tid = threadIdx.x;
    for (int e = tid; e < 4096; e += 256) {
        int rr = e >> 5;
        int d4 = (e & 31) * 4;
        *(float4*)&out[(size_t)(m0 + rr)*DMODEL + n0 + d4] = *(float4*)&Cs[rr*132 + d4];
    }
}

// ---------------- Flash attention (causal), 64x64 tiles, packed f32x2 ----------------
// Unchanged math; epilogue writes bf16 hi/lo (for the mma.sync out_proj).
__global__ __launch_bounds__(256, 2) void attn_kernel()
{
    float* sm = (float*)dynsm;
    float* Qt = sm;                 // [64 d][68]  Qt[d][m]  (Q/8)
    float* Kt = sm + 64*68;         // [64 d][68]  Kt[d][c]
    float* Vs = sm + 2*64*68;       // [64 c][68]  Vs[c][d]
    float* Ps = sm + 3*64*68;       // [64 c][68]  Ps[c][m]

    const int tid = threadIdx.x;
    const int tx  = tid & 15, ty = tid >> 4;
    const int tx4 = tx * 4,  ty4 = ty * 4;
    const int qt  = blockIdx.x;
    const int bh  = blockIdx.y;

    const float* Qg = g_q + (size_t)bh * SEQ * DHD;
    const float* Kg = g_k + (size_t)bh * SEQ * DHD;
    const float* Vg = g_v + (size_t)bh * SEQ * DHD;

    for (int i = tid; i < 1024; i += 256) {
        int m  = i >> 4;
        int d0 = (i & 15) << 2;
        float4 q = *(const float4*)&Qg[(size_t)(qt*64 + m)*DHD + d0];
        Qt[(d0+0)*68 + m] = q.x * 0.125f;
        Qt[(d0+1)*68 + m] = q.y * 0.125f;
        Qt[(d0+2)*68 + m] = q.z * 0.125f;
        Qt[(d0+3)*68 + m] = q.w * 0.125f;
    }

    float mi[4], li[4];
    unsigned long long accO[2][4];
#pragma unroll
    for (int i = 0; i < 4; ++i) { mi[i] = -INFINITY; li[i] = 0.f; }
#pragma unroll
    for (int p = 0; p < 2; ++p)
#pragma unroll
        for (int j = 0; j < 4; ++j) accO[p][j] = 0ull;

    for (int kt = 0; kt <= qt; ++kt) {
        __syncthreads();
        for (int i = tid; i < 1024; i += 256) {
            int c  = i >> 4;
            int d0 = (i & 15) << 2;
            float4 kv = *(const float4*)&Kg[(size_t)(kt*64 + c)*DHD + d0];
            Kt[(d0+0)*68 + c] = kv.x; Kt[(d0+1)*68 + c] = kv.y;
            Kt[(d0+2)*68 + c] = kv.z; Kt[(d0+3)*68 + c] = kv.w;
            float4 vv = *(const float4*)&Vg[(size_t)(kt*64 + c)*DHD + d0];
            *(float4*)&Vs[c*68 + d0] = vv;
        }
        __syncthreads();

        unsigned long long accS[2][4];
#pragma unroll
        for (int p = 0; p < 2; ++p)
#pragma unroll
            for (int j = 0; j < 4; ++j) accS[p][j] = 0ull;
#pragma unroll 8
        for (int d = 0; d < 64; ++d) {
            ulonglong2 ap = *(const ulonglong2*)&Qt[d*68 + ty4];
            float4 bv = *(const float4*)&Kt[d*68 + tx4];
            unsigned long long b0 = pack2(bv.x, bv.x);
            unsigned long long b1 = pack2(bv.y, bv.y);
            unsigned long long b2 = pack2(bv.z, bv.z);
            unsigned long long b3 = pack2(bv.w, bv.w);
            ffma2(accS[0][0], ap.x, b0); ffma2(accS[0][1], ap.x, b1);
            ffma2(accS[0][2], ap.x, b2); ffma2(accS[0][3], ap.x, b3);
            ffma2(accS[1][0], ap.y, b0); ffma2(accS[1][1], ap.y, b1);
            ffma2(accS[1][2], ap.y, b2); ffma2(accS[1][3], ap.y, b3);
        }

        float sc[4][4];
#pragma unroll
        for (int p = 0; p < 2; ++p)
#pragma unroll
            for (int j = 0; j < 4; ++j)
                unpack2(accS[p][j], sc[2*p][j], sc[2*p+1][j]);

        if (kt == qt) {
#pragma unroll
            for (int i = 0; i < 4; ++i)
#pragma unroll
                for (int j = 0; j < 4; ++j)
                    if (tx4 + j > ty4 + i) sc[i][j] = -INFINITY;
        }

        float pr[4][4], alpha[4];
#pragma unroll
        for (int i = 0; i < 4; ++i) {
            float v = fmaxf(fmaxf(sc[i][0], sc[i][1]), fmaxf(sc[i][2], sc[i][3]));
            v = fmaxf(v, __shfl_xor_sync(0xffffffffu, v, 1));
            v = fmaxf(v, __shfl_xor_sync(0xffffffffu, v, 2));
            v = fmaxf(v, __shfl_xor_sync(0xffffffffu, v, 4));
            v = fmaxf(v, __shfl_xor_sync(0xffffffffu, v, 8));
            float mn = fmaxf(mi[i], v);
            alpha[i] = __expf(mi[i] - mn);
            mi[i] = mn;
            float rs = 0.f;
#pragma unroll
            for (int j = 0; j < 4; ++j) {
                pr[i][j] = __expf(sc[i][j] - mn);
                rs += pr[i][j];
            }
            rs += __shfl_xor_sync(0xffffffffu, rs, 1);
            rs += __shfl_xor_sync(0xffffffffu, rs, 2);
            rs += __shfl_xor_sync(0xffffffffu, rs, 4);
            rs += __shfl_xor_sync(0xffffffffu, rs, 8);
            li[i] = li[i] * alpha[i] + rs;
        }

        {
            unsigned long long al0 = pack2(alpha[0], alpha[1]);
            unsigned long long al1 = pack2(alpha[2], alpha[3]);
#pragma unroll
            for (int j = 0; j < 4; ++j) { mul2(accO[0][j], al0); mul2(accO[1][j], al1); }
        }

#pragma unroll
        for (int j = 0; j < 4; ++j)
            *(float4*)&Ps[(tx4 + j)*68 + ty4] =
                make_float4(pr[0][j], pr[1][j], pr[2][j], pr[3][j]);
        __syncthreads();

#pragma unroll 8
        for (int c = 0; c < 64; ++c) {
            ulonglong2 ap = *(const ulonglong2*)&Ps[c*68 + ty4];
            float4 bv = *(const float4*)&Vs[c*68 + tx4];
            unsigned long long b0 = pack2(bv.x, bv.x);
            unsigned long long b1 = pack2(bv.y, bv.y);
            unsigned long long b2 = pack2(bv.z, bv.z);
            unsigned long long b3 = pack2(bv.w, bv.w);
            ffma2(accO[0][0], ap.x, b0); ffma2(accO[0][1], ap.x, b1);
            ffma2(accO[0][2], ap.x, b2); ffma2(accO[0][3], ap.x, b3);
            ffma2(accO[1][0], ap.y, b0); ffma2(accO[1][1], ap.y, b1);
            ffma2(accO[1][2], ap.y, b2); ffma2(accO[1][3], ap.y, b3);
        }
    }

    // write O (normalize by l) as bf16 hi/lo for the mma.sync out_proj
    const int b = bh >> 4, h = bh & 15;
    float o[4][4];
#pragma unroll
    for (int p = 0; p < 2; ++p)
#pragma unroll
        for (int j = 0; j < 4; ++j)
            unpack2(accO[p][j], o[2*p][j], o[2*p+1][j]);
#pragma unroll
    for (int i = 0; i < 4; ++i) {
        float inv = 1.0f / li[i];
        int s = qt*64 + ty4 + i;
        size_t idx = ((size_t)b*SEQ + s)*DMODEL + h*DHD + tx4;
        u16 h0,h1,h2,h3,l0,l1,l2,l3;
        split1(o[i][0]*inv, h0, l0);
        split1(o[i][1]*inv, h1, l1);
        split1(o[i][2]*inv, h2, l2);
        split1(o[i][3]*inv, h3, l3);
        *(uint2*)&g_aoh[idx] = make_uint2((u32)h0 | ((u32)h1<<16), (u32)h2 | ((u32)h3<<16));
        *(uint2*)&g_aol[idx] = make_uint2((u32)l0 | ((u32)l1<<16), (u32)l2 | ((u32)l3<<16));
    }
}

// ---------------- launch ----------------
extern "C" void kernel_launch(void* const* d_in, const int* in_sizes, int n_in,
                              void* d_out, int out_size)
{
    (void)in_sizes; (void)n_in; (void)out_size;
    const float* x    = (const float*)d_in[0];
    const float* qkvw = (const float*)d_in[1];
    const float* wo   = (const float*)d_in[2];
    float*       out  = (float*)d_out;

    rope_table_kernel<<<(SEQ*32 + 255)/256, 256>>>();
    cvt_x_kernel <<<(MTOT*DMODEL/4   + 255)/256, 256>>>(x);
    cvt_w_kernel <<<(N_QKV*DMODEL/4  + 255)/256, 256>>>(qkvw);
    cvt_wo_kernel<<<(DMODEL*DMODEL/4 + 255)/256, 256>>>(wo);

    cudaFuncSetAttribute(qkv_mma_kernel, cudaFuncAttributeMaxDynamicSharedMemorySize, MM_SMEM);
    qkv_mma_kernel<<<dim3(MTOT/128, N_QKV/128), 256, MM_SMEM>>>();

    const int attn_smem = 4 * 64 * 68 * 4;   // 69632 B
    cudaFuncSetAttribute(attn_kernel, cudaFuncAttributeMaxDynamicSharedMemorySize, attn_smem);
    attn_kernel<<<dim3(SEQ/64, BATCH*NH), 256, attn_smem>>>();

    cudaFuncSetAttribute(out_proj_mma_kernel, cudaFuncAttributeMaxDynamicSharedMemorySize, MM_SMEM);
    out_proj_mma_kernel<<<dim3(MTOT/128, DMODEL/128), 256, MM_SMEM>>>(out);
}

// round 13
// speedup vs baseline: 2.0105x; 1.1427x over previous
#include <cuda_runtime.h>
#include <cuda_bf16.h>
#include <math.h>
#include <stdint.h>

// Problem constants
#define BATCH 4
#define SEQ   2048
#define DMODEL 1024
#define NH    16
#define DHD   64
#define MTOT  (BATCH*SEQ)      // 8192
#define N_QKV (3*DMODEL)       // 3072

typedef unsigned short u16;
typedef unsigned int   u32;

// single dynamic-smem declaration shared by all kernels
extern __shared__ char dynsm[];

// ---------------- scratch (static device globals; no allocation) ----------------
__device__ __align__(16) float g_q [(size_t)BATCH*NH*SEQ*DHD];
__device__ __align__(16) float g_k [(size_t)BATCH*NH*SEQ*DHD];
__device__ __align__(16) float g_v [(size_t)BATCH*NH*SEQ*DHD];
__device__ __align__(16) u16 g_xh [(size_t)MTOT*DMODEL];
__device__ __align__(16) u16 g_xl [(size_t)MTOT*DMODEL];
__device__ __align__(16) u16 g_wh [(size_t)N_QKV*DMODEL];
__device__ __align__(16) u16 g_wl [(size_t)N_QKV*DMODEL];
__device__ __align__(16) u16 g_woh[(size_t)DMODEL*DMODEL];
__device__ __align__(16) u16 g_wol[(size_t)DMODEL*DMODEL];
__device__ __align__(16) u16 g_aoh[(size_t)MTOT*DMODEL];
__device__ __align__(16) u16 g_aol[(size_t)MTOT*DMODEL];
__device__ float g_cos[SEQ*32];
__device__ float g_sin[SEQ*32];

// ---------------- helpers ----------------
static __device__ __forceinline__ uint32_t smem_u32(const void* p) {
    uint32_t a;
    asm("{ .reg .u64 t; cvta.to.shared.u64 t, %1; cvt.u32.u64 %0, t; }" : "=r"(a) : "l"(p));
    return a;
}
// bf16 hi/lo split: x = hi + lo + O(2^-18 x)
static __device__ __forceinline__ void split1(float x, u16& h, u16& l) {
    __nv_bfloat16 hb = __float2bfloat16_rn(x);
    float hf = __bfloat162float(hb);
    __nv_bfloat16 lb = __float2bfloat16_rn(x - hf);
    h = __bfloat16_as_ushort(hb);
    l = __bfloat16_as_ushort(lb);
}
// split two floats -> packed bf16x2 hi + packed bf16x2 lo
static __device__ __forceinline__ void pksplit(float a, float b, u32& h, u32& l) {
    u16 ha, la, hb, lb;
    split1(a, ha, la);
    split1(b, hb, lb);
    h = (u32)ha | ((u32)hb << 16);
    l = (u32)la | ((u32)lb << 16);
}
static __device__ __forceinline__ void ldmx4(uint32_t* r, uint32_t a) {
    asm volatile("ldmatrix.sync.aligned.m8n8.x4.shared.b16 {%0,%1,%2,%3}, [%4];"
        : "=r"(r[0]), "=r"(r[1]), "=r"(r[2]), "=r"(r[3]) : "r"(a));
}
static __device__ __forceinline__ void mma_bf16(float* c, const uint32_t* a, const uint32_t* b) {
    asm volatile("mma.sync.aligned.m16n8k16.row.col.f32.bf16.bf16.f32 "
        "{%0,%1,%2,%3}, {%4,%5,%6,%7}, {%8,%9}, {%0,%1,%2,%3};"
        : "+f"(c[0]), "+f"(c[1]), "+f"(c[2]), "+f"(c[3])
        : "r"(a[0]), "r"(a[1]), "r"(a[2]), "r"(a[3]), "r"(b[0]), "r"(b[1]));
}

// ---------------- RoPE tables ----------------
__global__ void rope_table_kernel() {
    int idx = blockIdx.x * blockDim.x + threadIdx.x;
    if (idx >= SEQ * 32) return;
    int s = idx >> 5;
    int j = idx & 31;
    float invf = exp2f(-(float)j * 0.41524101186092f);  // 10000^(-j/32)
    float ang  = (float)s * invf;
    g_cos[idx] = (float)cos((double)ang);
    g_sin[idx] = (float)sin((double)ang);
}

// ---------------- bf16 hi/lo pre-split kernels ----------------
static __device__ __forceinline__ void cvt_body(const float* __restrict__ src,
                                                u16* __restrict__ dh, u16* __restrict__ dl, int n4) {
    int i = blockIdx.x * blockDim.x + threadIdx.x;
    if (i >= n4) return;
    float4 v = ((const float4*)src)[i];
    u16 h0,h1,h2,h3,l0,l1,l2,l3;
    split1(v.x,h0,l0); split1(v.y,h1,l1); split1(v.z,h2,l2); split1(v.w,h3,l3);
    ((uint2*)dh)[i] = make_uint2((u32)h0 | ((u32)h1<<16), (u32)h2 | ((u32)h3<<16));
    ((uint2*)dl)[i] = make_uint2((u32)l0 | ((u32)l1<<16), (u32)l2 | ((u32)l3<<16));
}
__global__ void cvt_x_kernel (const float* __restrict__ s){ cvt_body(s, g_xh,  g_xl,  MTOT*DMODEL/4); }
__global__ void cvt_w_kernel (const float* __restrict__ s){ cvt_body(s, g_wh,  g_wl,  N_QKV*DMODEL/4); }
__global__ void cvt_wo_kernel(const float* __restrict__ s){ cvt_body(s, g_woh, g_wol, DMODEL*DMODEL/4); }

// ============================================================================
// bf16-split mma.sync GEMM: C[128,128] = A[m0:,K] * B[n0:,K]^T, K=1024.
// (unchanged from R12 — validated)
// ============================================================================
#define MM_BUF  40960
#define MM_SMEM 81920

__device__ __forceinline__ void mma_mainloop(
    const u16* __restrict__ Ah, const u16* __restrict__ Al,
    const u16* __restrict__ Bh, const u16* __restrict__ Bl,
    int m0, int n0, char* sm, uint32_t smb, float c[4][4][4])
{
    const int tid  = threadIdx.x;
    const int lane = tid & 31;
    const int wid  = tid >> 5;
    const int wm   = wid >> 2;       // 0..1
    const int wn   = wid & 3;        // 0..3
    const int r    = tid & 127;

    const uint4* gh;
    const uint4* gl;
    int sregion;
    if (tid < 128) {
        gh = (const uint4*)(Ah + (size_t)(m0 + r) * DMODEL);
        gl = (const uint4*)(Al + (size_t)(m0 + r) * DMODEL);
        sregion = 0;
    } else {
        gh = (const uint4*)(Bh + (size_t)(n0 + r) * DMODEL);
        gl = (const uint4*)(Bl + (size_t)(n0 + r) * DMODEL);
        sregion = 20480;
    }
    char* sdh_row = sm + sregion + r * 80;
    char* sdl_row = sdh_row + 10240;

    uint4 vh[4], vl[4];
#pragma unroll
    for (int i = 0; i < 4; ++i) { vh[i] = gh[i]; vl[i] = gl[i]; }
#pragma unroll
    for (int i = 0; i < 4; ++i) {
        *(uint4*)(sdh_row + i*16) = vh[i];
        *(uint4*)(sdl_row + i*16) = vl[i];
    }
    __syncthreads();

    const int arow = (lane & 7) + ((lane >> 3) & 1) * 8;
    const int acol = (lane >> 4) * 16;
    const int brow = (lane & 7) + ((lane >> 4) & 1) * 8;
    const int bcol = ((lane >> 3) & 1) * 16;
    const uint32_t aBase = smb + (uint32_t)((wm*64 + arow) * 80 + acol);
    const uint32_t bBase = smb + 20480 + (uint32_t)((wn*32 + brow) * 80 + bcol);

    int buf = 0;
    for (int ch = 0; ch < 32; ++ch) {
        const bool nxt = (ch + 1 < 32);
        if (nxt) {
#pragma unroll
            for (int i = 0; i < 4; ++i) {
                vh[i] = gh[(ch+1)*4 + i];
                vl[i] = gl[(ch+1)*4 + i];
            }
        }
        const uint32_t bo = (uint32_t)(buf * MM_BUF);
#pragma unroll
        for (int s = 0; s < 2; ++s) {
            uint32_t ah[4][4], al[4][4], bh[4][2], bl[4][2];
#pragma unroll
            for (int mt = 0; mt < 4; ++mt) {
                ldmx4(ah[mt], aBase + bo + mt*1280 + s*32);
                ldmx4(al[mt], aBase + bo + mt*1280 + s*32 + 10240);
            }
#pragma unroll
            for (int p = 0; p < 2; ++p) {
                uint32_t t4[4];
                ldmx4(t4, bBase + bo + p*1280 + s*32);
                bh[2*p][0] = t4[0]; bh[2*p][1] = t4[1];
                bh[2*p+1][0] = t4[2]; bh[2*p+1][1] = t4[3];
                ldmx4(t4, bBase + bo + p*1280 + s*32 + 10240);
                bl[2*p][0] = t4[0]; bl[2*p][1] = t4[1];
                bl[2*p+1][0] = t4[2]; bl[2*p+1][1] = t4[3];
            }
#pragma unroll
            for (int mt = 0; mt < 4; ++mt)
#pragma unroll
                for (int nt = 0; nt < 4; ++nt) {
                    mma_bf16(c[mt][nt], ah[mt], bh[nt]);
                    mma_bf16(c[mt][nt], ah[mt], bl[nt]);
                    mma_bf16(c[mt][nt], al[mt], bh[nt]);
                }
        }
        if (nxt) {
            char* dh = sdh_row + ((buf ^ 1) * MM_BUF);
            char* dl = sdl_row + ((buf ^ 1) * MM_BUF);
#pragma unroll
            for (int i = 0; i < 4; ++i) {
                *(uint4*)(dh + i*16) = vh[i];
                *(uint4*)(dl + i*16) = vl[i];
            }
            __syncthreads();
        }
        buf ^= 1;
    }
    __syncthreads();
}

// store fragments to Cs[128][132]
__device__ __forceinline__ void frag_to_cs(float* Cs, float c[4][4][4]) {
    const int tid = threadIdx.x;
    const int lane = tid & 31;
    const int wid = tid >> 5;
    const int wm = wid >> 2, wn = wid & 3;
    const int tr = lane >> 2, tc = (lane & 3) * 2;
#pragma unroll
    for (int mt = 0; mt < 4; ++mt)
#pragma unroll
        for (int nt = 0; nt < 4; ++nt) {
            int rr = wm*64 + mt*16 + tr;
            int cc = wn*32 + nt*8 + tc;
            *(float2*)&Cs[rr*132 + cc]       = make_float2(c[mt][nt][0], c[mt][nt][1]);
            *(float2*)&Cs[(rr+8)*132 + cc]   = make_float2(c[mt][nt][2], c[mt][nt][3]);
        }
    __syncthreads();
}

// ---------------- QKV GEMM (mma.sync) + RoPE epilogue ----------------
__global__ __launch_bounds__(256, 1) void qkv_mma_kernel()
{
    char* sm = dynsm;
    uint32_t smb = smem_u32(sm);

    float c[4][4][4];
#pragma unroll
    for (int a = 0; a < 4; ++a)
#pragma unroll
        for (int b = 0; b < 4; ++b)
#pragma unroll
            for (int d = 0; d < 4; ++d) c[a][b][d] = 0.f;

    const int m0 = blockIdx.x * 128;
    const int nt = blockIdx.y;                  // 0..23
    mma_mainloop(g_xh, g_xl, g_wh, g_wl, m0, nt * 128, sm, smb, c);

    float* Cs = (float*)sm;
    frag_to_cs(Cs, c);

    const int tid = threadIdx.x;
    const int sel   = nt >> 3;                  // 0=Q 1=K 2=V
    const int hbase = (nt & 7) * 2;
    float* dst = (sel == 0) ? g_q : ((sel == 1) ? g_k : g_v);

    for (int e = tid; e < 8192; e += 256) {
        int rr = e >> 6;
        int d  = (e & 63) * 2;                  // even col 0..126
        int m = m0 + rr;
        int b = m >> 11, s = m & 2047;
        float2 v = *(float2*)&Cs[rr*132 + d];
        int head = hbase + (d >> 6);
        int dloc = d & 63;
        if (sel < 2) {
            float2 p = *(float2*)&Cs[rr*132 + (d ^ 32)];
            int j = d & 31;
            float c0 = g_cos[s*32 + j],   c1 = g_cos[s*32 + j + 1];
            float s0 = g_sin[s*32 + j],   s1 = g_sin[s*32 + j + 1];
            if (dloc < 32) { v.x = v.x*c0 - p.x*s0; v.y = v.y*c1 - p.y*s1; }
            else           { v.x = v.x*c0 + p.x*s0; v.y = v.y*c1 + p.y*s1; }
        }
        *(float2*)&dst[(((size_t)b*NH + head)*SEQ + s)*DHD + dloc] = v;
    }
}

// ---------------- out_proj (mma.sync): out = AO @ wo^T ----------------
__global__ __launch_bounds__(256, 1) void out_proj_mma_kernel(float* __restrict__ out)
{
    char* sm = dynsm;
    uint32_t smb = smem_u32(sm);

    float c[4][4][4];
#pragma unroll
    for (int a = 0; a < 4; ++a)
#pragma unroll
        for (int b = 0; b < 4; ++b)
#pragma unroll
            for (int d = 0; d < 4; ++d) c[a][b][d] = 0.f;

    const int m0 = blockIdx.x * 128;
    const int n0 = blockIdx.y * 128;
    mma_mainloop(g_aoh, g_aol, g_woh, g_wol, m0, n0, sm, smb, c);

    float* Cs = (float*)sm;
    frag_to_cs(Cs, c);

    const int tid = threadIdx.x;
    for (int e = tid; e < 4096; e += 256) {
        int rr = e >> 5;
        int d4 = (e & 31) * 4;
        *(float4*)&out[(size_t)(m0 + rr)*DMODEL + n0 + d4] = *(float4*)&Cs[rr*132 + d4];
    }
}

// ============================================================================
// Flash attention on mma.sync (causal). BM=128 (8 warps x m16), KV tile 64.
// S = QK^T 3-term bf16 split; softmax on C-fragments in registers;
// P packed to bf16 hi/lo in-register (C-frag == A-frag layout); P@V 3-term.
// smem rows stride 144B (ldmatrix banks 4r mod 32 -> conflict-free).
// ============================================================================
#define AQH 0
#define AQL 18432
#define AKH 36864
#define AKL 46080
#define AVH 55296
#define AVL 64512
#define ATTN_SMEM 73728

__global__ __launch_bounds__(256, 1) void attn_mma_kernel()
{
    char* sm = dynsm;
    uint32_t smb = smem_u32(sm);

    const int tid  = threadIdx.x;
    const int lane = tid & 31;
    const int wid  = tid >> 5;          // 0..7, warp owns q-rows 16*wid..+15
    const int qt   = blockIdx.x;        // 0..15 (128-row q tile)
    const int bh   = blockIdx.y;        // 0..63

    const float* Qg = g_q + ((size_t)bh * SEQ + qt * 128) * DHD;
    const float* Kg = g_k + (size_t)bh * SEQ * DHD;
    const float* Vg = g_v + (size_t)bh * SEQ * DHD;

    // ---- load Q tile 128x64, scale by 1/8, split hi/lo into smem ----
    for (int slot = tid; slot < 2048; slot += 256) {
        int r  = slot >> 4;
        int f4 = slot & 15;
        float4 v = ((const float4*)Qg)[slot];
        v.x *= 0.125f; v.y *= 0.125f; v.z *= 0.125f; v.w *= 0.125f;
        u32 h0, l0, h1, l1;
        pksplit(v.x, v.y, h0, l0);
        pksplit(v.z, v.w, h1, l1);
        *(uint2*)(sm + AQH + r*144 + f4*8) = make_uint2(h0, h1);
        *(uint2*)(sm + AQL + r*144 + f4*8) = make_uint2(l0, l1);
    }

    // ldmatrix lane addressing (same recipe as mma_mainloop — validated R12)
    const int arow = (lane & 7) + ((lane >> 3) & 1) * 8;
    const int acol = (lane >> 4) * 16;
    const int brow = (lane & 7) + ((lane >> 4) & 1) * 8;
    const int bcol = ((lane >> 3) & 1) * 16;
    const uint32_t aBaseH = smb + AQH + (uint32_t)((wid*16 + arow)*144 + acol);
    const uint32_t aBaseL = aBaseH + (AQL - AQH);
    const uint32_t kBase  = smb + AKH + (uint32_t)(brow*144 + bcol);
    const uint32_t vBase  = smb + AVH + (uint32_t)(brow*144 + bcol);

    const int rowTop = qt*128 + wid*16;
    const int r0     = rowTop + (lane >> 2);

    float mi0 = -INFINITY, mi1 = -INFINITY, li0 = 0.f, li1 = 0.f;
    float accO[8][4];
#pragma unroll
    for (int j = 0; j < 8; ++j)
#pragma unroll
        for (int d = 0; d < 4; ++d) accO[j][d] = 0.f;

    const int nkt = 2*qt + 2;
    for (int kt = 0; kt < nkt; ++kt) {
        __syncthreads();     // prior tile's smem reads complete
        // ---- load K and V tiles (64x64 fp32), split; V stored transposed ----
        for (int slot = tid; slot < 2048; slot += 256) {
            int cc = (slot & 1023) >> 4;
            int f4 = slot & 15;
            if (slot < 1024) {
                float4 v = ((const float4*)(Kg + (size_t)(kt*64 + cc)*DHD))[f4];
                u32 h0, l0, h1, l1;
                pksplit(v.x, v.y, h0, l0);
                pksplit(v.z, v.w, h1, l1);
                *(uint2*)(sm + AKH + cc*144 + f4*8) = make_uint2(h0, h1);
                *(uint2*)(sm + AKL + cc*144 + f4*8) = make_uint2(l0, l1);
            } else {
                float4 v = ((const float4*)(Vg + (size_t)(kt*64 + cc)*DHD))[f4];
                int d0 = f4 * 4;
                u16 hh, ll;
                split1(v.x, hh, ll);
                *(u16*)(sm + AVH + (d0+0)*144 + cc*2) = hh;
                *(u16*)(sm + AVL + (d0+0)*144 + cc*2) = ll;
                split1(v.y, hh, ll);
                *(u16*)(sm + AVH + (d0+1)*144 + cc*2) = hh;
                *(u16*)(sm + AVL + (d0+1)*144 + cc*2) = ll;
                split1(v.z, hh, ll);
                *(u16*)(sm + AVH + (d0+2)*144 + cc*2) = hh;
                *(u16*)(sm + AVL + (d0+2)*144 + cc*2) = ll;
                split1(v.w, hh, ll);
                *(u16*)(sm + AVH + (d0+3)*144 + cc*2) = hh;
                *(u16*)(sm + AVL + (d0+3)*144 + cc*2) = ll;
            }
        }
        __syncthreads();

        // ---- S = (Q/8) K^T : 3-term bf16 ----
        float accS[8][4];
#pragma unroll
        for (int j = 0; j < 8; ++j)
#pragma unroll
            for (int d = 0; d < 4; ++d) accS[j][d] = 0.f;

#pragma unroll
        for (int s = 0; s < 4; ++s) {
            u32 ah[4], al[4];
            ldmx4(ah, aBaseH + s*32);
            ldmx4(al, aBaseL + s*32);
#pragma unroll
            for (int g = 0; g < 4; ++g) {
                u32 th[4], tl[4];
                ldmx4(th, kBase + g*2304 + s*32);
                ldmx4(tl, kBase + (AKL-AKH) + g*2304 + s*32);
                mma_bf16(accS[2*g],   ah, th);
                mma_bf16(accS[2*g],   ah, tl);
                mma_bf16(accS[2*g],   al, th);
                mma_bf16(accS[2*g+1], ah, th+2);
                mma_bf16(accS[2*g+1], ah, tl+2);
                mma_bf16(accS[2*g+1], al, th+2);
            }
        }

        // ---- causal mask (only tiles crossing the diagonal) ----
        if (kt*64 + 63 > rowTop) {
#pragma unroll
            for (int j = 0; j < 8; ++j) {
                int cb = kt*64 + j*8 + 2*(lane & 3);
                if (cb     > r0)     accS[j][0] = -INFINITY;
                if (cb + 1 > r0)     accS[j][1] = -INFINITY;
                if (cb     > r0 + 8) accS[j][2] = -INFINITY;
                if (cb + 1 > r0 + 8) accS[j][3] = -INFINITY;
            }
        }

        // ---- online softmax on fragments (rows r0, r0+8) ----
        float mx0 = -INFINITY, mx1 = -INFINITY;
#pragma unroll
        for (int j = 0; j < 8; ++j) {
            mx0 = fmaxf(mx0, fmaxf(accS[j][0], accS[j][1]));
            mx1 = fmaxf(mx1, fmaxf(accS[j][2], accS[j][3]));
        }
        mx0 = fmaxf(mx0, __shfl_xor_sync(0xffffffffu, mx0, 1));
        mx0 = fmaxf(mx0, __shfl_xor_sync(0xffffffffu, mx0, 2));
        mx1 = fmaxf(mx1, __shfl_xor_sync(0xffffffffu, mx1, 1));
        mx1 = fmaxf(mx1, __shfl_xor_sync(0xffffffffu, mx1, 2));
        float nm0 = fmaxf(mi0, mx0), nm1 = fmaxf(mi1, mx1);
        float a0 = __expf(mi0 - nm0), a1 = __expf(mi1 - nm1);
        mi0 = nm0; mi1 = nm1;
        float s0 = 0.f, s1 = 0.f;
#pragma unroll
        for (int j = 0; j < 8; ++j) {
            accS[j][0] = __expf(accS[j][0] - nm0); s0 += accS[j][0];
            accS[j][1] = __expf(accS[j][1] - nm0); s0 += accS[j][1];
            accS[j][2] = __expf(accS[j][2] - nm1); s1 += accS[j][2];
            accS[j][3] = __expf(accS[j][3] - nm1); s1 += accS[j][3];
        }
        s0 += __shfl_xor_sync(0xffffffffu, s0, 1);
        s0 += __shfl_xor_sync(0xffffffffu, s0, 2);
        s1 += __shfl_xor_sync(0xffffffffu, s1, 1);
        s1 += __shfl_xor_sync(0xffffffffu, s1, 2);
        li0 = li0 * a0 + s0;
        li1 = li1 * a1 + s1;
#pragma unroll
        for (int j = 0; j < 8; ++j) {
            accO[j][0] *= a0; accO[j][1] *= a0;
            accO[j][2] *= a1; accO[j][3] *= a1;
        }

        // ---- O += P @ V : P from registers (C-frag == A-frag layout), 3-term ----
#pragma unroll
        for (int t = 0; t < 4; ++t) {
            u32 ph[4], pl[4];
            pksplit(accS[2*t][0],   accS[2*t][1],   ph[0], pl[0]);
            pksplit(accS[2*t][2],   accS[2*t][3],   ph[1], pl[1]);
            pksplit(accS[2*t+1][0], accS[2*t+1][1], ph[2], pl[2]);
            pksplit(accS[2*t+1][2], accS[2*t+1][3], ph[3], pl[3]);
#pragma unroll
            for (int g = 0; g < 4; ++g) {
                u32 th[4], tl[4];
                ldmx4(th, vBase + g*2304 + t*32);
                ldmx4(tl, vBase + (AVL-AVH) + g*2304 + t*32);
                mma_bf16(accO[2*g],   ph, th);
                mma_bf16(accO[2*g],   ph, tl);
                mma_bf16(accO[2*g],   pl, th);
                mma_bf16(accO[2*g+1], ph, th+2);
                mma_bf16(accO[2*g+1], ph, tl+2);
                mma_bf16(accO[2*g+1], pl, th+2);
            }
        }
    }

    // ---- epilogue: normalize, split to bf16 hi/lo for out_proj ----
    const float inv0 = 1.0f / li0, inv1 = 1.0f / li1;
    const int b = bh >> 4, h = bh & 15;
    const int srow = qt*128 + wid*16 + (lane >> 2);
    const size_t base0 = ((size_t)b*SEQ + srow)*DMODEL + h*DHD + 2*(lane & 3);
    const size_t base1 = base0 + (size_t)8*DMODEL;
#pragma unroll
    for (int j = 0; j < 8; ++j) {
        u32 hh, ll;
        pksplit(accO[j][0]*inv0, accO[j][1]*inv0, hh, ll);
        *(u32*)&g_aoh[base0 + j*8] = hh;
        *(u32*)&g_aol[base0 + j*8] = ll;
        pksplit(accO[j][2]*inv1, accO[j][3]*inv1, hh, ll);
        *(u32*)&g_aoh[base1 + j*8] = hh;
        *(u32*)&g_aol[base1 + j*8] = ll;
    }
}

// ---------------- launch ----------------
extern "C" void kernel_launch(void* const* d_in, const int* in_sizes, int n_in,
                              void* d_out, int out_size)
{
    (void)in_sizes; (void)n_in; (void)out_size;
    const float* x    = (const float*)d_in[0];
    const float* qkvw = (const float*)d_in[1];
    const float* wo   = (const float*)d_in[2];
    float*       out  = (float*)d_out;

    rope_table_kernel<<<(SEQ*32 + 255)/256, 256>>>();
    cvt_x_kernel <<<(MTOT*DMODEL/4   + 255)/256, 256>>>(x);
    cvt_w_kernel <<<(N_QKV*DMODEL/4  + 255)/256, 256>>>(qkvw);
    cvt_wo_kernel<<<(DMODEL*DMODEL/4 + 255)/256, 256>>>(wo);

    cudaFuncSetAttribute(qkv_mma_kernel, cudaFuncAttributeMaxDynamicSharedMemorySize, MM_SMEM);
    qkv_mma_kernel<<<dim3(MTOT/128, N_QKV/128), 256, MM_SMEM>>>();

    cudaFuncSetAttribute(attn_mma_kernel, cudaFuncAttributeMaxDynamicSharedMemorySize, ATTN_SMEM);
    attn_mma_kernel<<<dim3(SEQ/128, BATCH*NH), 256, ATTN_SMEM>>>();

    cudaFuncSetAttribute(out_proj_mma_kernel, cudaFuncAttributeMaxDynamicSharedMemorySize, MM_SMEM);
    out_proj_mma_kernel<<<dim3(MTOT/128, DMODEL/128), 256, MM_SMEM>>>(out);
}